// round 5
// baseline (speedup 1.0000x reference)
#include <cuda_runtime.h>
#include <cuda_bf16.h>
#include <cstdint>
#include <math.h>

typedef unsigned int u32;

#define B_   2
#define T_   2048
#define C_   1024
#define H_   16
#define D_   64
#define NTOK (B_*T_)
#define DFF  4096
#define C3   (3*C_)

// ---------------- scratch (no allocation allowed) ----------------
__device__ __nv_bfloat16 g_hb  [NTOK*C_];
__device__ __nv_bfloat16 g_h2b [NTOK*C_];
__device__ __nv_bfloat16 g_qkv [NTOK*C3];
__device__ __nv_bfloat16 g_attb[NTOK*C_];
__device__ __nv_bfloat16 g_f1b [(size_t)NTOK*DFF];
__device__ float         g_x1  [NTOK*C_];
__device__ __nv_bfloat16 g_wqkv[C_*C3];
__device__ __nv_bfloat16 g_wo  [C_*C_];
__device__ __nv_bfloat16 g_wf1 [C_*DFF];
__device__ __nv_bfloat16 g_wf2 [DFF*C_];
__device__ float         g_bqkv[C3];

// ---------------- small helpers ----------------
__device__ __forceinline__ u32 pack_bf16(float x, float y) {
    __nv_bfloat162 t = __floats2bfloat162_rn(x, y);
    u32 r; memcpy(&r, &t, 4); return r;
}
__device__ __forceinline__ void cp16(u32 sdst, const void* gsrc) {
    asm volatile("cp.async.cg.shared.global [%0], [%1], 16;" :: "r"(sdst), "l"(gsrc));
}
__device__ __forceinline__ void cp_commit() { asm volatile("cp.async.commit_group;"); }
__device__ __forceinline__ void ldsm_x4(u32& r0, u32& r1, u32& r2, u32& r3, u32 addr) {
    asm volatile("ldmatrix.sync.aligned.m8n8.x4.shared.b16 {%0,%1,%2,%3},[%4];"
                 : "=r"(r0), "=r"(r1), "=r"(r2), "=r"(r3) : "r"(addr));
}
__device__ __forceinline__ void ldsm_x4_t(u32& r0, u32& r1, u32& r2, u32& r3, u32 addr) {
    asm volatile("ldmatrix.sync.aligned.m8n8.x4.trans.shared.b16 {%0,%1,%2,%3},[%4];"
                 : "=r"(r0), "=r"(r1), "=r"(r2), "=r"(r3) : "r"(addr));
}
__device__ __forceinline__ void mma_bf16(float* c, const u32* a, u32 b0, u32 b1) {
    asm volatile("mma.sync.aligned.m16n8k16.row.col.f32.bf16.bf16.f32 "
                 "{%0,%1,%2,%3},{%4,%5,%6,%7},{%8,%9},{%0,%1,%2,%3};"
                 : "+f"(c[0]), "+f"(c[1]), "+f"(c[2]), "+f"(c[3])
                 : "r"(a[0]), "r"(a[1]), "r"(a[2]), "r"(a[3]), "r"(b0), "r"(b1));
}
// FFMA-only exp (no MUFU).
__device__ __forceinline__ float fexp(float x) {
    x = fmaxf(x, -80.0f);
    float y = x * 1.4426950408889634f;
    float k = rintf(y);
    float t = (y - k) * 0.6931471805599453f;
    float p = fmaf(t, fmaf(t, fmaf(t, fmaf(t, fmaf(t, 8.3333333e-3f, 4.1666667e-2f),
                 0.16666667f), 0.5f), 1.0f), 1.0f);
    int ki = (int)k;
    return __int_as_float(__float_as_int(p) + (ki << 23));
}

// ---------------- weight conversion ----------------
__global__ void cvt_qkv_kernel(const float* __restrict__ qw, const float* __restrict__ kw,
                               const float* __restrict__ vw, const float* __restrict__ qb,
                               const float* __restrict__ kb, const float* __restrict__ vb)
{
    int gtid = blockIdx.x * blockDim.x + threadIdx.x;
    int stride = gridDim.x * blockDim.x;
    for (int i = gtid; i < C_*C_/4; i += stride) {
        int c = i / (C_/4), j = (i % (C_/4)) * 4;
        float4 q4 = *(const float4*)(qw + (size_t)c*C_ + j);
        float4 k4 = *(const float4*)(kw + (size_t)c*C_ + j);
        float4 v4 = *(const float4*)(vw + (size_t)c*C_ + j);
        *(uint2*)(g_wqkv + (size_t)c*C3 + j)        = make_uint2(pack_bf16(q4.x,q4.y), pack_bf16(q4.z,q4.w));
        *(uint2*)(g_wqkv + (size_t)c*C3 + C_ + j)   = make_uint2(pack_bf16(k4.x,k4.y), pack_bf16(k4.z,k4.w));
        *(uint2*)(g_wqkv + (size_t)c*C3 + 2*C_ + j) = make_uint2(pack_bf16(v4.x,v4.y), pack_bf16(v4.z,v4.w));
    }
    if (gtid < C_) {
        g_bqkv[gtid]        = qb[gtid];
        g_bqkv[C_ + gtid]   = kb[gtid];
        g_bqkv[2*C_ + gtid] = vb[gtid];
    }
}
__global__ void cvt_kernel(const float* __restrict__ src, __nv_bfloat16* __restrict__ dst, int n4)
{
    int gtid = blockIdx.x * blockDim.x + threadIdx.x;
    int stride = gridDim.x * blockDim.x;
    for (int i = gtid; i < n4; i += stride) {
        float4 s = *(const float4*)(src + (size_t)i*4);
        *(uint2*)(dst + (size_t)i*4) = make_uint2(pack_bf16(s.x,s.y), pack_bf16(s.z,s.w));
    }
}

// ---------------- LayerNorm: fp32 in -> bf16 out ----------------
__global__ void __launch_bounds__(256) ln_kernel(const float* __restrict__ x,
                                                 const float* __restrict__ w,
                                                 const float* __restrict__ b,
                                                 __nv_bfloat16* __restrict__ y)
{
    __shared__ float red[8];
    int row = blockIdx.x, tid = threadIdx.x;
    const float* xr = x + (size_t)row * C_;
    float4 v = *(const float4*)(xr + 4*tid);

    float s = v.x + v.y + v.z + v.w;
#pragma unroll
    for (int o = 16; o > 0; o >>= 1) s += __shfl_xor_sync(~0u, s, o);
    if ((tid & 31) == 0) red[tid >> 5] = s;
    __syncthreads();
    if (tid < 32) {
        float t = (tid < 8) ? red[tid] : 0.f;
#pragma unroll
        for (int o = 4; o > 0; o >>= 1) t += __shfl_xor_sync(~0u, t, o);
        if (tid == 0) red[0] = t;
    }
    __syncthreads();
    float mu = red[0] * (1.0f / C_);
    __syncthreads();

    float dx = v.x-mu, dy = v.y-mu, dz = v.z-mu, dw = v.w-mu;
    float sq = dx*dx + dy*dy + dz*dz + dw*dw;
#pragma unroll
    for (int o = 16; o > 0; o >>= 1) sq += __shfl_xor_sync(~0u, sq, o);
    if ((tid & 31) == 0) red[tid >> 5] = sq;
    __syncthreads();
    if (tid < 32) {
        float t = (tid < 8) ? red[tid] : 0.f;
#pragma unroll
        for (int o = 4; o > 0; o >>= 1) t += __shfl_xor_sync(~0u, t, o);
        if (tid == 0) red[0] = t;
    }
    __syncthreads();
    float rs = rsqrtf(red[0] * (1.0f / C_) + 1e-5f);
    float4 w4 = *(const float4*)(w + 4*tid);
    float4 b4 = *(const float4*)(b + 4*tid);
    float o0 = dx*rs*w4.x + b4.x, o1 = dy*rs*w4.y + b4.y;
    float o2 = dz*rs*w4.z + b4.z, o3 = dw*rs*w4.w + b4.w;
    *(uint2*)(y + (size_t)row*C_ + 4*tid) = make_uint2(pack_bf16(o0,o1), pack_bf16(o2,o3));
}

// ---------------- GEMM 256x128x32, bf16 MMA, 3-stage cp.async ----------------
// warp grid 4(m) x 2(n); warp tile 64x64
// MODE 0: out = acc + bias               (OBF: bf16 out)
// MODE 1: out = resid + gamma*(acc+bias) (fp32 out)
// MODE 2: out = gelu(acc + bias)         (bf16 out)
#define GA_ROWB   80                    // A smem row bytes: 64 data + 16 pad
#define GB_ROWB   272                   // B smem row bytes: 256 data + 16 pad
#define GA_BYTES  (256*GA_ROWB)         // 20480
#define GB_BYTES  (32*GB_ROWB)          // 8704
#define STAGE_B   (GA_BYTES + GB_BYTES) // 29184
#define NSTAGE    3
#define GEMM_SMEM (NSTAGE*STAGE_B)      // 87552

template<int MODE, int OBF>
__global__ void __launch_bounds__(256) bgemm_kernel(
    const __nv_bfloat16* __restrict__ A, const __nv_bfloat16* __restrict__ Bw,
    const float* __restrict__ bias,
    const float* __restrict__ resid, const float* __restrict__ gamma,
    void* __restrict__ CoutV, int M, int N, int K)
{
    extern __shared__ char gsm[];
    const u32 smb = (u32)__cvta_generic_to_shared(gsm);

    const int tid  = threadIdx.x;
    const int lane = tid & 31, warp = tid >> 5;
    const int warp_m = warp >> 1, warp_n = warp & 1;
    const int m_blk = blockIdx.y << 8, n_blk = blockIdx.x << 7;

    // cp.async assignments
    const int ar = tid >> 2, ac = tid & 3;       // A: rows 0..63 (x4), 4x16B cols
    const int br = tid >> 4, bc = tid & 15;      // B: rows 0..15 (x2), 16x16B cols
    const __nv_bfloat16* Ag = A  + (size_t)(m_blk + ar) * K + ac*8;
    const __nv_bfloat16* Bg = Bw + (size_t)br * N + n_blk + bc*8;
    const u32 dA0 = smb + ar*GA_ROWB + ac*16;
    const u32 dB0 = smb + GA_BYTES + br*GB_ROWB + bc*16;

    // ldmatrix base addressing
    const int g  = lane >> 3;
    const int r8 = lane & 7;
    const u32 aAddr0 = smb + (u32)(warp_m*64 + r8 + (g&1)*8) * GA_ROWB + (u32)((g>>1)*16);
    const u32 bAddr0 = smb + GA_BYTES + (u32)(r8 + (g&1)*8) * GB_ROWB
                           + (u32)(warp_n*64 + (g>>1)*8) * 2;

    float acc[4][8][4];
#pragma unroll
    for (int mt = 0; mt < 4; mt++)
#pragma unroll
        for (int nt = 0; nt < 8; nt++)
#pragma unroll
            for (int i = 0; i < 4; i++) acc[mt][nt][i] = 0.f;

    const int nk = K >> 5;

    // issue stage for k-tile kt into buffer kt%3
    auto issue = [&](int kt) {
        const u32 sb = (kt % NSTAGE) * STAGE_B;
        const __nv_bfloat16* Ak = Ag + (kt << 5);
        const __nv_bfloat16* Bk = Bg + (size_t)(kt << 5) * N;
#pragma unroll
        for (int j = 0; j < 4; j++)
            cp16(dA0 + sb + j*64*GA_ROWB, Ak + (size_t)(j*64)*K);
#pragma unroll
        for (int j = 0; j < 2; j++)
            cp16(dB0 + sb + j*16*GB_ROWB, Bk + (size_t)(j*16)*N);
        cp_commit();
    };

    issue(0);
    if (nk > 1) issue(1);

    for (int kt = 0; kt < nk; kt++) {
        if (kt + 1 < nk) asm volatile("cp.async.wait_group 1;");
        else             asm volatile("cp.async.wait_group 0;");
        __syncthreads();

        if (kt + 2 < nk) issue(kt + 2);

        const u32 sb = (kt % NSTAGE) * STAGE_B;
        const u32 aB = aAddr0 + sb;
        const u32 bB = bAddr0 + sb;
#pragma unroll
        for (int ks = 0; ks < 2; ks++) {
            u32 af[4][4];
#pragma unroll
            for (int mt = 0; mt < 4; mt++)
                ldsm_x4(af[mt][0], af[mt][1], af[mt][2], af[mt][3],
                        aB + (u32)(mt*16) * GA_ROWB + (u32)(ks*32));
#pragma unroll
            for (int np = 0; np < 4; np++) {
                u32 b0, b1, b2, b3;
                ldsm_x4_t(b0, b1, b2, b3,
                          bB + (u32)(ks*16) * GB_ROWB + (u32)(np*32));
#pragma unroll
                for (int mt = 0; mt < 4; mt++) {
                    mma_bf16(acc[mt][2*np],   af[mt], b0, b1);
                    mma_bf16(acc[mt][2*np+1], af[mt], b2, b3);
                }
            }
        }
        __syncthreads();
    }

    // ---- epilogue ----
    const int rr = lane >> 2, cc = (lane & 3) << 1;
    const int row0 = m_blk + warp_m * 64;
    const int col0 = n_blk + warp_n * 64;
#pragma unroll
    for (int mt = 0; mt < 4; mt++) {
#pragma unroll
        for (int nt = 0; nt < 8; nt++) {
            const int col = col0 + nt * 8 + cc;
            float2 b2 = *(const float2*)(bias + col);
            float2 g2 = make_float2(0.f, 0.f);
            if (MODE == 1) g2 = *(const float2*)(gamma + col);
#pragma unroll
            for (int half = 0; half < 2; half++) {
                const int row = row0 + mt * 16 + rr + half * 8;
                const size_t off = (size_t)row * N + col;
                float v0 = acc[mt][nt][half*2 + 0] + b2.x;
                float v1 = acc[mt][nt][half*2 + 1] + b2.y;
                if (MODE == 1) {
                    float2 rv = *(const float2*)(resid + off);
                    v0 = rv.x + g2.x * v0;
                    v1 = rv.y + g2.y * v1;
                } else if (MODE == 2) {
                    v0 = 0.5f * v0 * (1.0f + erff(v0 * 0.70710678118654752f));
                    v1 = 0.5f * v1 * (1.0f + erff(v1 * 0.70710678118654752f));
                }
                if (OBF) *(u32*)((__nv_bfloat16*)CoutV + off) = pack_bf16(v0, v1);
                else     *(float2*)((float*)CoutV + off) = make_float2(v0, v1);
            }
        }
    }
}

// ---------------- Flash attention: bf16 MMA, fp32 softmax ----------------
#define KV_ROWB  144
#define TILE_B   (64*KV_ROWB)
#define SQ_OFF   0
#define SK_OFF   (TILE_B)
#define SV_OFF   (3*TILE_B)
#define SMSK_OFF (5*TILE_B)
#define ATTN_SMEM (5*TILE_B + 2*64*4)

__device__ __forceinline__ void attn_issue_kv(const __nv_bfloat16* __restrict__ qkv,
                                              u32 smb, int buf, int kt, int b, int h, int tid)
{
    const __nv_bfloat16* gK = qkv + ((size_t)(b*T_) + kt*64) * C3 + C_ + h*D_;
    const __nv_bfloat16* gV = gK + C_;
    u32 dK = smb + SK_OFF + buf*TILE_B;
    u32 dV = smb + SV_OFF + buf*TILE_B;
#pragma unroll
    for (int k = 0; k < 4; k++) {
        int c = tid + k*128;
        int row = c >> 3, col16 = c & 7;
        cp16(dK + row*KV_ROWB + col16*16, gK + (size_t)row*C3 + col16*8);
        cp16(dV + row*KV_ROWB + col16*16, gV + (size_t)row*C3 + col16*8);
    }
}

__global__ void __launch_bounds__(128) attn_kernel(
    const __nv_bfloat16* __restrict__ qkv, const int* __restrict__ mask,
    __nv_bfloat16* __restrict__ Out)
{
    extern __shared__ char attn_sm[];
    u32 smb = (u32)__cvta_generic_to_shared(attn_sm);
    float* sMask = (float*)(attn_sm + SMSK_OFF);

    const int tid = threadIdx.x;
    const int lane = tid & 31, warp = tid >> 5;
    const int b = blockIdx.z, h = blockIdx.y;
    const int q0 = blockIdx.x << 6;
    const int g = lane >> 3, r8 = lane & 7;
    const int qd = lane >> 2, qi = lane & 3;

    {
        const __nv_bfloat16* gQ = qkv + ((size_t)(b*T_ + q0)) * C3 + h*D_;
#pragma unroll
        for (int k = 0; k < 4; k++) {
            int c = tid + k*128;
            int row = c >> 3, col16 = c & 7;
            cp16(smb + SQ_OFF + row*KV_ROWB + col16*16, gQ + (size_t)row*C3 + col16*8);
        }
        attn_issue_kv(qkv, smb, 0, 0, b, h, tid);
        if (tid < 64) sMask[tid] = mask[b*T_ + tid] ? 0.f : -1e30f;
        cp_commit();
    }

    float ofrag[8][4];
#pragma unroll
    for (int nt = 0; nt < 8; nt++)
#pragma unroll
        for (int i = 0; i < 4; i++) ofrag[nt][i] = 0.f;
    float mrow0 = -1e30f, mrow1 = -1e30f, lrow0 = 0.f, lrow1 = 0.f;
    u32 qf[4][4];

    const int NKT = T_ / 64;
    for (int kt = 0; kt < NKT; kt++) {
        const int cur = kt & 1;
        if (kt + 1 < NKT) {
            attn_issue_kv(qkv, smb, cur ^ 1, kt + 1, b, h, tid);
            if (tid < 64) sMask[(cur^1)*64 + tid] = mask[b*T_ + (kt+1)*64 + tid] ? 0.f : -1e30f;
            cp_commit();
            asm volatile("cp.async.wait_group 1;");
        } else {
            asm volatile("cp.async.wait_group 0;");
        }
        __syncthreads();

        if (kt == 0) {
#pragma unroll
            for (int ks = 0; ks < 4; ks++) {
                u32 addr = smb + SQ_OFF
                         + (u32)(warp*16 + r8 + (g&1)*8) * KV_ROWB
                         + (u32)(ks*16 + (g>>1)*8) * 2;
                ldsm_x4(qf[ks][0], qf[ks][1], qf[ks][2], qf[ks][3], addr);
            }
        }

        float sfrag[8][4];
#pragma unroll
        for (int nt = 0; nt < 8; nt++)
#pragma unroll
            for (int i = 0; i < 4; i++) sfrag[nt][i] = 0.f;
        const u32 kBase = smb + SK_OFF + cur*TILE_B;
#pragma unroll
        for (int ks = 0; ks < 4; ks++) {
#pragma unroll
            for (int np = 0; np < 4; np++) {
                u32 k0, k1, k2, k3;
                u32 addr = kBase + (u32)(np*16 + (g>>1)*8 + r8) * KV_ROWB
                                 + (u32)(ks*16 + (g&1)*8) * 2;
                ldsm_x4(k0, k1, k2, k3, addr);
                mma_bf16(sfrag[2*np],   qf[ks], k0, k1);
                mma_bf16(sfrag[2*np+1], qf[ks], k2, k3);
            }
        }

        const float* msk = sMask + cur*64;
        float mx0 = -1e30f, mx1 = -1e30f;
#pragma unroll
        for (int nt = 0; nt < 8; nt++) {
            float2 am = *(const float2*)(msk + nt*8 + 2*qi);
            sfrag[nt][0] = fmaf(sfrag[nt][0], 0.125f, am.x);
            sfrag[nt][1] = fmaf(sfrag[nt][1], 0.125f, am.y);
            sfrag[nt][2] = fmaf(sfrag[nt][2], 0.125f, am.x);
            sfrag[nt][3] = fmaf(sfrag[nt][3], 0.125f, am.y);
            mx0 = fmaxf(mx0, fmaxf(sfrag[nt][0], sfrag[nt][1]));
            mx1 = fmaxf(mx1, fmaxf(sfrag[nt][2], sfrag[nt][3]));
        }
        mx0 = fmaxf(mx0, __shfl_xor_sync(~0u, mx0, 1));
        mx0 = fmaxf(mx0, __shfl_xor_sync(~0u, mx0, 2));
        mx1 = fmaxf(mx1, __shfl_xor_sync(~0u, mx1, 1));
        mx1 = fmaxf(mx1, __shfl_xor_sync(~0u, mx1, 2));
        float mnew0 = fmaxf(mrow0, mx0), mnew1 = fmaxf(mrow1, mx1);
        float cor0 = fexp(mrow0 - mnew0), cor1 = fexp(mrow1 - mnew1);
        mrow0 = mnew0; mrow1 = mnew1;
        float ps0 = 0.f, ps1 = 0.f;
#pragma unroll
        for (int nt = 0; nt < 8; nt++) {
            sfrag[nt][0] = fexp(sfrag[nt][0] - mnew0);
            sfrag[nt][1] = fexp(sfrag[nt][1] - mnew0);
            sfrag[nt][2] = fexp(sfrag[nt][2] - mnew1);
            sfrag[nt][3] = fexp(sfrag[nt][3] - mnew1);
            ps0 += sfrag[nt][0] + sfrag[nt][1];
            ps1 += sfrag[nt][2] + sfrag[nt][3];
        }
        ps0 += __shfl_xor_sync(~0u, ps0, 1);
        ps0 += __shfl_xor_sync(~0u, ps0, 2);
        ps1 += __shfl_xor_sync(~0u, ps1, 1);
        ps1 += __shfl_xor_sync(~0u, ps1, 2);
        lrow0 = lrow0 * cor0 + ps0;
        lrow1 = lrow1 * cor1 + ps1;
#pragma unroll
        for (int nt = 0; nt < 8; nt++) {
            ofrag[nt][0] *= cor0; ofrag[nt][1] *= cor0;
            ofrag[nt][2] *= cor1; ofrag[nt][3] *= cor1;
        }

        const u32 vBase = smb + SV_OFF + cur*TILE_B;
#pragma unroll
        for (int kk = 0; kk < 4; kk++) {
            u32 a[4];
            a[0] = pack_bf16(sfrag[2*kk][0],   sfrag[2*kk][1]);
            a[1] = pack_bf16(sfrag[2*kk][2],   sfrag[2*kk][3]);
            a[2] = pack_bf16(sfrag[2*kk+1][0], sfrag[2*kk+1][1]);
            a[3] = pack_bf16(sfrag[2*kk+1][2], sfrag[2*kk+1][3]);
#pragma unroll
            for (int dp = 0; dp < 4; dp++) {
                u32 v0, v1, v2, v3;
                u32 addr = vBase + (u32)(kk*16 + r8 + (g&1)*8) * KV_ROWB
                                 + (u32)(dp*16 + (g>>1)*8) * 2;
                ldsm_x4_t(v0, v1, v2, v3, addr);
                mma_bf16(ofrag[2*dp],   a, v0, v1);
                mma_bf16(ofrag[2*dp+1], a, v2, v3);
            }
        }
        __syncthreads();
    }

    const float inv0 = 1.0f / lrow0, inv1 = 1.0f / lrow1;
    const int r0 = q0 + warp*16 + qd;
    const int r1 = r0 + 8;
    __nv_bfloat16* o0 = Out + (size_t)(b*T_ + r0) * C_ + h*D_ + 2*qi;
    __nv_bfloat16* o1 = Out + (size_t)(b*T_ + r1) * C_ + h*D_ + 2*qi;
#pragma unroll
    for (int nt = 0; nt < 8; nt++) {
        *(u32*)(o0 + nt*8) = pack_bf16(ofrag[nt][0]*inv0, ofrag[nt][1]*inv0);
        *(u32*)(o1 + nt*8) = pack_bf16(ofrag[nt][2]*inv1, ofrag[nt][3]*inv1);
    }
}

// ---------------- host launcher ----------------
extern "C" void kernel_launch(void* const* d_in, const int* in_sizes, int n_in,
                              void* d_out, int out_size)
{
    const float* x    = (const float*)d_in[0];
    const int*   mask = (const int*)  d_in[1];
    const float* ln1w = (const float*)d_in[2];
    const float* ln1b = (const float*)d_in[3];
    const float* ln2w = (const float*)d_in[4];
    const float* ln2b = (const float*)d_in[5];
    const float* qw   = (const float*)d_in[6];
    const float* qb   = (const float*)d_in[7];
    const float* kw   = (const float*)d_in[8];
    const float* kb   = (const float*)d_in[9];
    const float* vw   = (const float*)d_in[10];
    const float* vb   = (const float*)d_in[11];
    const float* ow   = (const float*)d_in[12];
    const float* ob   = (const float*)d_in[13];
    const float* f1w  = (const float*)d_in[14];
    const float* f1b  = (const float*)d_in[15];
    const float* f2w  = (const float*)d_in[16];
    const float* f2b  = (const float*)d_in[17];
    const float* gm1  = (const float*)d_in[18];
    const float* gm2  = (const float*)d_in[19];
    float* out = (float*)d_out;

    __nv_bfloat16 *b_h, *b_h2, *b_qkv, *b_att, *b_f1, *b_wqkv, *b_wo, *b_wf1, *b_wf2;
    float *b_x1, *b_bqkv;
    cudaGetSymbolAddress((void**)&b_h,    g_hb);
    cudaGetSymbolAddress((void**)&b_h2,   g_h2b);
    cudaGetSymbolAddress((void**)&b_qkv,  g_qkv);
    cudaGetSymbolAddress((void**)&b_att,  g_attb);
    cudaGetSymbolAddress((void**)&b_f1,   g_f1b);
    cudaGetSymbolAddress((void**)&b_x1,   g_x1);
    cudaGetSymbolAddress((void**)&b_wqkv, g_wqkv);
    cudaGetSymbolAddress((void**)&b_wo,   g_wo);
    cudaGetSymbolAddress((void**)&b_wf1,  g_wf1);
    cudaGetSymbolAddress((void**)&b_wf2,  g_wf2);
    cudaGetSymbolAddress((void**)&b_bqkv, g_bqkv);

    cudaFuncSetAttribute(attn_kernel,
                         cudaFuncAttributeMaxDynamicSharedMemorySize, ATTN_SMEM);
    cudaFuncSetAttribute(bgemm_kernel<0,1>,
                         cudaFuncAttributeMaxDynamicSharedMemorySize, GEMM_SMEM);
    cudaFuncSetAttribute(bgemm_kernel<1,0>,
                         cudaFuncAttributeMaxDynamicSharedMemorySize, GEMM_SMEM);
    cudaFuncSetAttribute(bgemm_kernel<2,1>,
                         cudaFuncAttributeMaxDynamicSharedMemorySize, GEMM_SMEM);

    cvt_qkv_kernel<<<1024, 256>>>(qw, kw, vw, qb, kb, vb);
    cvt_kernel<<<1024, 256>>>(ow,  b_wo,  C_*C_/4);
    cvt_kernel<<<2048, 256>>>(f1w, b_wf1, C_*DFF/4);
    cvt_kernel<<<2048, 256>>>(f2w, b_wf2, DFF*C_/4);

    dim3 gridQKV(C3 / 128, NTOK / 256);
    dim3 gridC  (C_ / 128, NTOK / 256);
    dim3 gridF  (DFF / 128, NTOK / 256);

    ln_kernel<<<NTOK, 256>>>(x, ln1w, ln1b, b_h);
    bgemm_kernel<0,1><<<gridQKV, 256, GEMM_SMEM>>>(b_h, b_wqkv, b_bqkv, nullptr, nullptr, b_qkv, NTOK, C3, C_);
    attn_kernel<<<dim3(T_/64, H_, B_), 128, ATTN_SMEM>>>(b_qkv, mask, b_att);
    bgemm_kernel<1,0><<<gridC, 256, GEMM_SMEM>>>(b_att, b_wo, ob, x, gm1, b_x1, NTOK, C_, C_);
    ln_kernel<<<NTOK, 256>>>(b_x1, ln2w, ln2b, b_h2);
    bgemm_kernel<2,1><<<gridF, 256, GEMM_SMEM>>>(b_h2, b_wf1, f1b, nullptr, nullptr, b_f1, NTOK, DFF, C_);
    bgemm_kernel<1,0><<<gridC, 256, GEMM_SMEM>>>(b_f1, b_wf2, f2b, b_x1, gm2, out, NTOK, C_, DFF);
}

// round 6
// speedup vs baseline: 1.0686x; 1.0686x over previous
#include <cuda_runtime.h>
#include <cuda_bf16.h>
#include <cstdint>
#include <math.h>

typedef unsigned int u32;

#define B_   2
#define T_   2048
#define C_   1024
#define H_   16
#define D_   64
#define NTOK (B_*T_)
#define DFF  4096
#define C3   (3*C_)

// ---------------- scratch (no allocation allowed) ----------------
__device__ __nv_bfloat16 g_hb  [NTOK*C_];
__device__ __nv_bfloat16 g_h2b [NTOK*C_];
__device__ __nv_bfloat16 g_qkv [NTOK*C3];
__device__ __nv_bfloat16 g_attb[NTOK*C_];
__device__ __nv_bfloat16 g_f1b [(size_t)NTOK*DFF];
__device__ float         g_x1  [NTOK*C_];
__device__ __nv_bfloat16 g_wqkv[C_*C3];
__device__ __nv_bfloat16 g_wo  [C_*C_];
__device__ __nv_bfloat16 g_wf1 [C_*DFF];
__device__ __nv_bfloat16 g_wf2 [DFF*C_];
__device__ float         g_bqkv[C3];

// ---------------- small helpers ----------------
__device__ __forceinline__ u32 pack_bf16(float x, float y) {
    __nv_bfloat162 t = __floats2bfloat162_rn(x, y);
    u32 r; memcpy(&r, &t, 4); return r;
}
__device__ __forceinline__ void cp16(u32 sdst, const void* gsrc) {
    asm volatile("cp.async.cg.shared.global [%0], [%1], 16;" :: "r"(sdst), "l"(gsrc));
}
__device__ __forceinline__ void cp_commit() { asm volatile("cp.async.commit_group;"); }
__device__ __forceinline__ void ldsm_x4(u32& r0, u32& r1, u32& r2, u32& r3, u32 addr) {
    asm volatile("ldmatrix.sync.aligned.m8n8.x4.shared.b16 {%0,%1,%2,%3},[%4];"
                 : "=r"(r0), "=r"(r1), "=r"(r2), "=r"(r3) : "r"(addr));
}
__device__ __forceinline__ void ldsm_x4_t(u32& r0, u32& r1, u32& r2, u32& r3, u32 addr) {
    asm volatile("ldmatrix.sync.aligned.m8n8.x4.trans.shared.b16 {%0,%1,%2,%3},[%4];"
                 : "=r"(r0), "=r"(r1), "=r"(r2), "=r"(r3) : "r"(addr));
}
__device__ __forceinline__ void mma_bf16(float* c, const u32* a, u32 b0, u32 b1) {
    asm volatile("mma.sync.aligned.m16n8k16.row.col.f32.bf16.bf16.f32 "
                 "{%0,%1,%2,%3},{%4,%5,%6,%7},{%8,%9},{%0,%1,%2,%3};"
                 : "+f"(c[0]), "+f"(c[1]), "+f"(c[2]), "+f"(c[3])
                 : "r"(a[0]), "r"(a[1]), "r"(a[2]), "r"(a[3]), "r"(b0), "r"(b1));
}
// FFMA-only exp (no MUFU).
__device__ __forceinline__ float fexp(float x) {
    x = fmaxf(x, -80.0f);
    float y = x * 1.4426950408889634f;
    float k = rintf(y);
    float t = (y - k) * 0.6931471805599453f;
    float p = fmaf(t, fmaf(t, fmaf(t, fmaf(t, fmaf(t, 8.3333333e-3f, 4.1666667e-2f),
                 0.16666667f), 0.5f), 1.0f), 1.0f);
    int ki = (int)k;
    return __int_as_float(__float_as_int(p) + (ki << 23));
}

// ---------------- weight conversion ----------------
__global__ void cvt_qkv_kernel(const float* __restrict__ qw, const float* __restrict__ kw,
                               const float* __restrict__ vw, const float* __restrict__ qb,
                               const float* __restrict__ kb, const float* __restrict__ vb)
{
    int gtid = blockIdx.x * blockDim.x + threadIdx.x;
    int stride = gridDim.x * blockDim.x;
    for (int i = gtid; i < C_*C_/4; i += stride) {
        int c = i / (C_/4), j = (i % (C_/4)) * 4;
        float4 q4 = *(const float4*)(qw + (size_t)c*C_ + j);
        float4 k4 = *(const float4*)(kw + (size_t)c*C_ + j);
        float4 v4 = *(const float4*)(vw + (size_t)c*C_ + j);
        *(uint2*)(g_wqkv + (size_t)c*C3 + j)        = make_uint2(pack_bf16(q4.x,q4.y), pack_bf16(q4.z,q4.w));
        *(uint2*)(g_wqkv + (size_t)c*C3 + C_ + j)   = make_uint2(pack_bf16(k4.x,k4.y), pack_bf16(k4.z,k4.w));
        *(uint2*)(g_wqkv + (size_t)c*C3 + 2*C_ + j) = make_uint2(pack_bf16(v4.x,v4.y), pack_bf16(v4.z,v4.w));
    }
    if (gtid < C_) {
        g_bqkv[gtid]        = qb[gtid];
        g_bqkv[C_ + gtid]   = kb[gtid];
        g_bqkv[2*C_ + gtid] = vb[gtid];
    }
}
__global__ void cvt_kernel(const float* __restrict__ src, __nv_bfloat16* __restrict__ dst, int n4)
{
    int gtid = blockIdx.x * blockDim.x + threadIdx.x;
    int stride = gridDim.x * blockDim.x;
    for (int i = gtid; i < n4; i += stride) {
        float4 s = *(const float4*)(src + (size_t)i*4);
        *(uint2*)(dst + (size_t)i*4) = make_uint2(pack_bf16(s.x,s.y), pack_bf16(s.z,s.w));
    }
}

// ---------------- LayerNorm: fp32 in -> bf16 out ----------------
__global__ void __launch_bounds__(256) ln_kernel(const float* __restrict__ x,
                                                 const float* __restrict__ w,
                                                 const float* __restrict__ b,
                                                 __nv_bfloat16* __restrict__ y)
{
    __shared__ float red[8];
    int row = blockIdx.x, tid = threadIdx.x;
    const float* xr = x + (size_t)row * C_;
    float4 v = *(const float4*)(xr + 4*tid);

    float s = v.x + v.y + v.z + v.w;
#pragma unroll
    for (int o = 16; o > 0; o >>= 1) s += __shfl_xor_sync(~0u, s, o);
    if ((tid & 31) == 0) red[tid >> 5] = s;
    __syncthreads();
    if (tid < 32) {
        float t = (tid < 8) ? red[tid] : 0.f;
#pragma unroll
        for (int o = 4; o > 0; o >>= 1) t += __shfl_xor_sync(~0u, t, o);
        if (tid == 0) red[0] = t;
    }
    __syncthreads();
    float mu = red[0] * (1.0f / C_);
    __syncthreads();

    float dx = v.x-mu, dy = v.y-mu, dz = v.z-mu, dw = v.w-mu;
    float sq = dx*dx + dy*dy + dz*dz + dw*dw;
#pragma unroll
    for (int o = 16; o > 0; o >>= 1) sq += __shfl_xor_sync(~0u, sq, o);
    if ((tid & 31) == 0) red[tid >> 5] = sq;
    __syncthreads();
    if (tid < 32) {
        float t = (tid < 8) ? red[tid] : 0.f;
#pragma unroll
        for (int o = 4; o > 0; o >>= 1) t += __shfl_xor_sync(~0u, t, o);
        if (tid == 0) red[0] = t;
    }
    __syncthreads();
    float rs = rsqrtf(red[0] * (1.0f / C_) + 1e-5f);
    float4 w4 = *(const float4*)(w + 4*tid);
    float4 b4 = *(const float4*)(b + 4*tid);
    float o0 = dx*rs*w4.x + b4.x, o1 = dy*rs*w4.y + b4.y;
    float o2 = dz*rs*w4.z + b4.z, o3 = dw*rs*w4.w + b4.w;
    *(uint2*)(y + (size_t)row*C_ + 4*tid) = make_uint2(pack_bf16(o0,o1), pack_bf16(o2,o3));
}

// ---------------- GEMM 128x128x32, bf16 MMA, 4-stage cp.async ----------------
// warp grid 2(m) x 4(n); warp tile 64x32; 2 CTAs/SM
// MODE 0: out = acc + bias               (OBF: bf16 out)
// MODE 1: out = resid + gamma*(acc+bias) (fp32 out)
// MODE 2: out = gelu(acc + bias)         (bf16 out)
#define GA_ROWB   80                    // A smem row: 64B data + 16 pad
#define GB_ROWB   272                   // B smem row: 256B data + 16 pad
#define GA_BYTES  (128*GA_ROWB)         // 10240
#define GB_BYTES  (32*GB_ROWB)          // 8704
#define STAGE_B   (GA_BYTES + GB_BYTES) // 18944
#define NSTAGE    4
#define GEMM_SMEM (NSTAGE*STAGE_B)      // 75776

template<int MODE, int OBF>
__global__ void __launch_bounds__(256) bgemm_kernel(
    const __nv_bfloat16* __restrict__ A, const __nv_bfloat16* __restrict__ Bw,
    const float* __restrict__ bias,
    const float* __restrict__ resid, const float* __restrict__ gamma,
    void* __restrict__ CoutV, int M, int N, int K)
{
    extern __shared__ char gsm[];
    const u32 smb = (u32)__cvta_generic_to_shared(gsm);

    const int tid  = threadIdx.x;
    const int lane = tid & 31, warp = tid >> 5;
    const int warp_m = warp >> 2, warp_n = warp & 3;
    const int m_blk = blockIdx.y << 7, n_blk = blockIdx.x << 7;

    // cp.async assignments (2 x 16B per thread for A, 2 for B)
    const int ar = tid >> 2, ac = tid & 3;       // A rows 0..63 (+64)
    const int br = tid >> 4, bc = tid & 15;      // B rows 0..15 (+16)
    const __nv_bfloat16* Ag = A  + (size_t)(m_blk + ar) * K + ac*8;
    const __nv_bfloat16* Bg = Bw + (size_t)br * N + n_blk + bc*8;
    const u32 dA0 = smb + ar*GA_ROWB + ac*16;
    const u32 dB0 = smb + GA_BYTES + br*GB_ROWB + bc*16;

    // ldmatrix base addressing
    const int g  = lane >> 3;
    const int r8 = lane & 7;
    const u32 aAddr0 = smb + (u32)(warp_m*64 + r8 + (g&1)*8) * GA_ROWB + (u32)((g>>1)*16);
    const u32 bAddr0 = smb + GA_BYTES + (u32)(r8 + (g&1)*8) * GB_ROWB
                           + (u32)(warp_n*32 + (g>>1)*8) * 2;

    float acc[4][4][4];
#pragma unroll
    for (int mt = 0; mt < 4; mt++)
#pragma unroll
        for (int nt = 0; nt < 4; nt++)
#pragma unroll
            for (int i = 0; i < 4; i++) acc[mt][nt][i] = 0.f;

    const int nk = K >> 5;

    auto issue = [&](int kt) {
        const u32 sb = (kt & (NSTAGE-1)) * STAGE_B;
        const __nv_bfloat16* Ak = Ag + (kt << 5);
        const __nv_bfloat16* Bk = Bg + (size_t)(kt << 5) * N;
        cp16(dA0 + sb,               Ak);
        cp16(dA0 + sb + 64*GA_ROWB,  Ak + (size_t)64*K);
        cp16(dB0 + sb,               Bk);
        cp16(dB0 + sb + 16*GB_ROWB,  Bk + (size_t)16*N);
        cp_commit();
    };

    issue(0);
    if (nk > 1) issue(1);
    if (nk > 2) issue(2);

    for (int kt = 0; kt < nk; kt++) {
        if      (kt + 2 < nk) asm volatile("cp.async.wait_group 2;");
        else if (kt + 1 < nk) asm volatile("cp.async.wait_group 1;");
        else                  asm volatile("cp.async.wait_group 0;");
        __syncthreads();   // single barrier per iter: stage (kt+3)%4 was read in iter kt-1

        if (kt + 3 < nk) issue(kt + 3);

        const u32 sb = (kt & (NSTAGE-1)) * STAGE_B;
        const u32 aB = aAddr0 + sb;
        const u32 bB = bAddr0 + sb;
#pragma unroll
        for (int ks = 0; ks < 2; ks++) {
            u32 af[4][4];
#pragma unroll
            for (int mt = 0; mt < 4; mt++)
                ldsm_x4(af[mt][0], af[mt][1], af[mt][2], af[mt][3],
                        aB + (u32)(mt*16) * GA_ROWB + (u32)(ks*32));
            u32 bf0[4], bf1[4];
            ldsm_x4_t(bf0[0], bf0[1], bf0[2], bf0[3], bB + (u32)(ks*16) * GB_ROWB);
            ldsm_x4_t(bf1[0], bf1[1], bf1[2], bf1[3], bB + (u32)(ks*16) * GB_ROWB + 32);
#pragma unroll
            for (int mt = 0; mt < 4; mt++) {
                mma_bf16(acc[mt][0], af[mt], bf0[0], bf0[1]);
                mma_bf16(acc[mt][1], af[mt], bf0[2], bf0[3]);
                mma_bf16(acc[mt][2], af[mt], bf1[0], bf1[1]);
                mma_bf16(acc[mt][3], af[mt], bf1[2], bf1[3]);
            }
        }
    }

    // ---- epilogue ----
    const int rr = lane >> 2, cc = (lane & 3) << 1;
    const int row0 = m_blk + warp_m * 64;
    const int col0 = n_blk + warp_n * 32;
#pragma unroll
    for (int mt = 0; mt < 4; mt++) {
#pragma unroll
        for (int nt = 0; nt < 4; nt++) {
            const int col = col0 + nt * 8 + cc;
            float2 b2 = *(const float2*)(bias + col);
            float2 g2 = make_float2(0.f, 0.f);
            if (MODE == 1) g2 = *(const float2*)(gamma + col);
#pragma unroll
            for (int half = 0; half < 2; half++) {
                const int row = row0 + mt * 16 + rr + half * 8;
                const size_t off = (size_t)row * N + col;
                float v0 = acc[mt][nt][half*2 + 0] + b2.x;
                float v1 = acc[mt][nt][half*2 + 1] + b2.y;
                if (MODE == 1) {
                    float2 rv = *(const float2*)(resid + off);
                    v0 = rv.x + g2.x * v0;
                    v1 = rv.y + g2.y * v1;
                } else if (MODE == 2) {
                    v0 = 0.5f * v0 * (1.0f + erff(v0 * 0.70710678118654752f));
                    v1 = 0.5f * v1 * (1.0f + erff(v1 * 0.70710678118654752f));
                }
                if (OBF) *(u32*)((__nv_bfloat16*)CoutV + off) = pack_bf16(v0, v1);
                else     *(float2*)((float*)CoutV + off) = make_float2(v0, v1);
            }
        }
    }
}

// ---------------- Flash attention: bf16 MMA, fp32 softmax ----------------
#define KV_ROWB  144
#define TILE_B   (64*KV_ROWB)
#define SQ_OFF   0
#define SK_OFF   (TILE_B)
#define SV_OFF   (3*TILE_B)
#define SMSK_OFF (5*TILE_B)
#define ATTN_SMEM (5*TILE_B + 2*64*4)

__device__ __forceinline__ void attn_issue_kv(const __nv_bfloat16* __restrict__ qkv,
                                              u32 smb, int buf, int kt, int b, int h, int tid)
{
    const __nv_bfloat16* gK = qkv + ((size_t)(b*T_) + kt*64) * C3 + C_ + h*D_;
    const __nv_bfloat16* gV = gK + C_;
    u32 dK = smb + SK_OFF + buf*TILE_B;
    u32 dV = smb + SV_OFF + buf*TILE_B;
#pragma unroll
    for (int k = 0; k < 4; k++) {
        int c = tid + k*128;
        int row = c >> 3, col16 = c & 7;
        cp16(dK + row*KV_ROWB + col16*16, gK + (size_t)row*C3 + col16*8);
        cp16(dV + row*KV_ROWB + col16*16, gV + (size_t)row*C3 + col16*8);
    }
}

__global__ void __launch_bounds__(128) attn_kernel(
    const __nv_bfloat16* __restrict__ qkv, const int* __restrict__ mask,
    __nv_bfloat16* __restrict__ Out)
{
    extern __shared__ char attn_sm[];
    u32 smb = (u32)__cvta_generic_to_shared(attn_sm);
    float* sMask = (float*)(attn_sm + SMSK_OFF);

    const int tid = threadIdx.x;
    const int lane = tid & 31, warp = tid >> 5;
    const int b = blockIdx.z, h = blockIdx.y;
    const int q0 = blockIdx.x << 6;
    const int g = lane >> 3, r8 = lane & 7;
    const int qd = lane >> 2, qi = lane & 3;

    {
        const __nv_bfloat16* gQ = qkv + ((size_t)(b*T_ + q0)) * C3 + h*D_;
#pragma unroll
        for (int k = 0; k < 4; k++) {
            int c = tid + k*128;
            int row = c >> 3, col16 = c & 7;
            cp16(smb + SQ_OFF + row*KV_ROWB + col16*16, gQ + (size_t)row*C3 + col16*8);
        }
        attn_issue_kv(qkv, smb, 0, 0, b, h, tid);
        if (tid < 64) sMask[tid] = mask[b*T_ + tid] ? 0.f : -1e30f;
        cp_commit();
    }

    float ofrag[8][4];
#pragma unroll
    for (int nt = 0; nt < 8; nt++)
#pragma unroll
        for (int i = 0; i < 4; i++) ofrag[nt][i] = 0.f;
    float mrow0 = -1e30f, mrow1 = -1e30f, lrow0 = 0.f, lrow1 = 0.f;
    u32 qf[4][4];

    const int NKT = T_ / 64;
    for (int kt = 0; kt < NKT; kt++) {
        const int cur = kt & 1;
        if (kt + 1 < NKT) {
            attn_issue_kv(qkv, smb, cur ^ 1, kt + 1, b, h, tid);
            if (tid < 64) sMask[(cur^1)*64 + tid] = mask[b*T_ + (kt+1)*64 + tid] ? 0.f : -1e30f;
            cp_commit();
            asm volatile("cp.async.wait_group 1;");
        } else {
            asm volatile("cp.async.wait_group 0;");
        }
        __syncthreads();

        if (kt == 0) {
#pragma unroll
            for (int ks = 0; ks < 4; ks++) {
                u32 addr = smb + SQ_OFF
                         + (u32)(warp*16 + r8 + (g&1)*8) * KV_ROWB
                         + (u32)(ks*16 + (g>>1)*8) * 2;
                ldsm_x4(qf[ks][0], qf[ks][1], qf[ks][2], qf[ks][3], addr);
            }
        }

        float sfrag[8][4];
#pragma unroll
        for (int nt = 0; nt < 8; nt++)
#pragma unroll
            for (int i = 0; i < 4; i++) sfrag[nt][i] = 0.f;
        const u32 kBase = smb + SK_OFF + cur*TILE_B;
#pragma unroll
        for (int ks = 0; ks < 4; ks++) {
#pragma unroll
            for (int np = 0; np < 4; np++) {
                u32 k0, k1, k2, k3;
                u32 addr = kBase + (u32)(np*16 + (g>>1)*8 + r8) * KV_ROWB
                                 + (u32)(ks*16 + (g&1)*8) * 2;
                ldsm_x4(k0, k1, k2, k3, addr);
                mma_bf16(sfrag[2*np],   qf[ks], k0, k1);
                mma_bf16(sfrag[2*np+1], qf[ks], k2, k3);
            }
        }

        const float* msk = sMask + cur*64;
        float mx0 = -1e30f, mx1 = -1e30f;
#pragma unroll
        for (int nt = 0; nt < 8; nt++) {
            float2 am = *(const float2*)(msk + nt*8 + 2*qi);
            sfrag[nt][0] = fmaf(sfrag[nt][0], 0.125f, am.x);
            sfrag[nt][1] = fmaf(sfrag[nt][1], 0.125f, am.y);
            sfrag[nt][2] = fmaf(sfrag[nt][2], 0.125f, am.x);
            sfrag[nt][3] = fmaf(sfrag[nt][3], 0.125f, am.y);
            mx0 = fmaxf(mx0, fmaxf(sfrag[nt][0], sfrag[nt][1]));
            mx1 = fmaxf(mx1, fmaxf(sfrag[nt][2], sfrag[nt][3]));
        }
        mx0 = fmaxf(mx0, __shfl_xor_sync(~0u, mx0, 1));
        mx0 = fmaxf(mx0, __shfl_xor_sync(~0u, mx0, 2));
        mx1 = fmaxf(mx1, __shfl_xor_sync(~0u, mx1, 1));
        mx1 = fmaxf(mx1, __shfl_xor_sync(~0u, mx1, 2));
        float mnew0 = fmaxf(mrow0, mx0), mnew1 = fmaxf(mrow1, mx1);
        float cor0 = fexp(mrow0 - mnew0), cor1 = fexp(mrow1 - mnew1);
        mrow0 = mnew0; mrow1 = mnew1;
        float ps0 = 0.f, ps1 = 0.f;
#pragma unroll
        for (int nt = 0; nt < 8; nt++) {
            sfrag[nt][0] = fexp(sfrag[nt][0] - mnew0);
            sfrag[nt][1] = fexp(sfrag[nt][1] - mnew0);
            sfrag[nt][2] = fexp(sfrag[nt][2] - mnew1);
            sfrag[nt][3] = fexp(sfrag[nt][3] - mnew1);
            ps0 += sfrag[nt][0] + sfrag[nt][1];
            ps1 += sfrag[nt][2] + sfrag[nt][3];
        }
        ps0 += __shfl_xor_sync(~0u, ps0, 1);
        ps0 += __shfl_xor_sync(~0u, ps0, 2);
        ps1 += __shfl_xor_sync(~0u, ps1, 1);
        ps1 += __shfl_xor_sync(~0u, ps1, 2);
        lrow0 = lrow0 * cor0 + ps0;
        lrow1 = lrow1 * cor1 + ps1;
#pragma unroll
        for (int nt = 0; nt < 8; nt++) {
            ofrag[nt][0] *= cor0; ofrag[nt][1] *= cor0;
            ofrag[nt][2] *= cor1; ofrag[nt][3] *= cor1;
        }

        const u32 vBase = smb + SV_OFF + cur*TILE_B;
#pragma unroll
        for (int kk = 0; kk < 4; kk++) {
            u32 a[4];
            a[0] = pack_bf16(sfrag[2*kk][0],   sfrag[2*kk][1]);
            a[1] = pack_bf16(sfrag[2*kk][2],   sfrag[2*kk][3]);
            a[2] = pack_bf16(sfrag[2*kk+1][0], sfrag[2*kk+1][1]);
            a[3] = pack_bf16(sfrag[2*kk+1][2], sfrag[2*kk+1][3]);
#pragma unroll
            for (int dp = 0; dp < 4; dp++) {
                u32 v0, v1, v2, v3;
                u32 addr = vBase + (u32)(kk*16 + r8 + (g&1)*8) * KV_ROWB
                                 + (u32)(dp*16 + (g>>1)*8) * 2;
                ldsm_x4_t(v0, v1, v2, v3, addr);
                mma_bf16(ofrag[2*dp],   a, v0, v1);
                mma_bf16(ofrag[2*dp+1], a, v2, v3);
            }
        }
        __syncthreads();
    }

    const float inv0 = 1.0f / lrow0, inv1 = 1.0f / lrow1;
    const int r0 = q0 + warp*16 + qd;
    const int r1 = r0 + 8;
    __nv_bfloat16* o0 = Out + (size_t)(b*T_ + r0) * C_ + h*D_ + 2*qi;
    __nv_bfloat16* o1 = Out + (size_t)(b*T_ + r1) * C_ + h*D_ + 2*qi;
#pragma unroll
    for (int nt = 0; nt < 8; nt++) {
        *(u32*)(o0 + nt*8) = pack_bf16(ofrag[nt][0]*inv0, ofrag[nt][1]*inv0);
        *(u32*)(o1 + nt*8) = pack_bf16(ofrag[nt][2]*inv1, ofrag[nt][3]*inv1);
    }
}

// ---------------- host launcher ----------------
extern "C" void kernel_launch(void* const* d_in, const int* in_sizes, int n_in,
                              void* d_out, int out_size)
{
    const float* x    = (const float*)d_in[0];
    const int*   mask = (const int*)  d_in[1];
    const float* ln1w = (const float*)d_in[2];
    const float* ln1b = (const float*)d_in[3];
    const float* ln2w = (const float*)d_in[4];
    const float* ln2b = (const float*)d_in[5];
    const float* qw   = (const float*)d_in[6];
    const float* qb   = (const float*)d_in[7];
    const float* kw   = (const float*)d_in[8];
    const float* kb   = (const float*)d_in[9];
    const float* vw   = (const float*)d_in[10];
    const float* vb   = (const float*)d_in[11];
    const float* ow   = (const float*)d_in[12];
    const float* ob   = (const float*)d_in[13];
    const float* f1w  = (const float*)d_in[14];
    const float* f1b  = (const float*)d_in[15];
    const float* f2w  = (const float*)d_in[16];
    const float* f2b  = (const float*)d_in[17];
    const float* gm1  = (const float*)d_in[18];
    const float* gm2  = (const float*)d_in[19];
    float* out = (float*)d_out;

    __nv_bfloat16 *b_h, *b_h2, *b_qkv, *b_att, *b_f1, *b_wqkv, *b_wo, *b_wf1, *b_wf2;
    float *b_x1, *b_bqkv;
    cudaGetSymbolAddress((void**)&b_h,    g_hb);
    cudaGetSymbolAddress((void**)&b_h2,   g_h2b);
    cudaGetSymbolAddress((void**)&b_qkv,  g_qkv);
    cudaGetSymbolAddress((void**)&b_att,  g_attb);
    cudaGetSymbolAddress((void**)&b_f1,   g_f1b);
    cudaGetSymbolAddress((void**)&b_x1,   g_x1);
    cudaGetSymbolAddress((void**)&b_wqkv, g_wqkv);
    cudaGetSymbolAddress((void**)&b_wo,   g_wo);
    cudaGetSymbolAddress((void**)&b_wf1,  g_wf1);
    cudaGetSymbolAddress((void**)&b_wf2,  g_wf2);
    cudaGetSymbolAddress((void**)&b_bqkv, g_bqkv);

    cudaFuncSetAttribute(attn_kernel,
                         cudaFuncAttributeMaxDynamicSharedMemorySize, ATTN_SMEM);
    cudaFuncSetAttribute(bgemm_kernel<0,1>,
                         cudaFuncAttributeMaxDynamicSharedMemorySize, GEMM_SMEM);
    cudaFuncSetAttribute(bgemm_kernel<1,0>,
                         cudaFuncAttributeMaxDynamicSharedMemorySize, GEMM_SMEM);
    cudaFuncSetAttribute(bgemm_kernel<2,1>,
                         cudaFuncAttributeMaxDynamicSharedMemorySize, GEMM_SMEM);

    cvt_qkv_kernel<<<1024, 256>>>(qw, kw, vw, qb, kb, vb);
    cvt_kernel<<<1024, 256>>>(ow,  b_wo,  C_*C_/4);
    cvt_kernel<<<2048, 256>>>(f1w, b_wf1, C_*DFF/4);
    cvt_kernel<<<2048, 256>>>(f2w, b_wf2, DFF*C_/4);

    dim3 gridQKV(C3 / 128, NTOK / 128);
    dim3 gridC  (C_ / 128, NTOK / 128);
    dim3 gridF  (DFF / 128, NTOK / 128);

    ln_kernel<<<NTOK, 256>>>(x, ln1w, ln1b, b_h);
    bgemm_kernel<0,1><<<gridQKV, 256, GEMM_SMEM>>>(b_h, b_wqkv, b_bqkv, nullptr, nullptr, b_qkv, NTOK, C3, C_);
    attn_kernel<<<dim3(T_/64, H_, B_), 128, ATTN_SMEM>>>(b_qkv, mask, b_att);
    bgemm_kernel<1,0><<<gridC, 256, GEMM_SMEM>>>(b_att, b_wo, ob, x, gm1, b_x1, NTOK, C_, C_);
    ln_kernel<<<NTOK, 256>>>(b_x1, ln2w, ln2b, b_h2);
    bgemm_kernel<2,1><<<gridF, 256, GEMM_SMEM>>>(b_h2, b_wf1, f1b, nullptr, nullptr, b_f1, NTOK, DFF, C_);
    bgemm_kernel<1,0><<<gridC, 256, GEMM_SMEM>>>(b_f1, b_wf2, f2b, b_x1, gm2, out, NTOK, C_, DFF);
}

// round 8
// speedup vs baseline: 1.1567x; 1.0824x over previous
#include <cuda_runtime.h>
#include <cuda_bf16.h>
#include <cstdint>
#include <math.h>

typedef unsigned int u32;

#define B_   2
#define T_   2048
#define C_   1024
#define H_   16
#define D_   64
#define NTOK (B_*T_)
#define DFF  4096
#define C3   (3*C_)

// ---------------- scratch (no allocation allowed) ----------------
__device__ __nv_bfloat16 g_hb  [NTOK*C_];
__device__ __nv_bfloat16 g_h2b [NTOK*C_];
__device__ __nv_bfloat16 g_qkv [NTOK*C3];
__device__ __nv_bfloat16 g_attb[NTOK*C_];
__device__ __nv_bfloat16 g_f1b [(size_t)NTOK*DFF];
__device__ float         g_x1  [NTOK*C_];
__device__ __nv_bfloat16 g_wqkv[C_*C3];
__device__ __nv_bfloat16 g_wo  [C_*C_];
__device__ __nv_bfloat16 g_wf1 [C_*DFF];
__device__ __nv_bfloat16 g_wf2 [DFF*C_];
__device__ float         g_bqkv[C3];

// ---------------- small helpers ----------------
__device__ __forceinline__ u32 pack_bf16(float x, float y) {
    __nv_bfloat162 t = __floats2bfloat162_rn(x, y);
    u32 r; memcpy(&r, &t, 4); return r;
}
__device__ __forceinline__ void cp16(u32 sdst, const void* gsrc) {
    asm volatile("cp.async.cg.shared.global [%0], [%1], 16;" :: "r"(sdst), "l"(gsrc));
}
__device__ __forceinline__ void cp_commit() { asm volatile("cp.async.commit_group;"); }
__device__ __forceinline__ void ldsm_x4(u32& r0, u32& r1, u32& r2, u32& r3, u32 addr) {
    asm volatile("ldmatrix.sync.aligned.m8n8.x4.shared.b16 {%0,%1,%2,%3},[%4];"
                 : "=r"(r0), "=r"(r1), "=r"(r2), "=r"(r3) : "r"(addr));
}
__device__ __forceinline__ void ldsm_x4_t(u32& r0, u32& r1, u32& r2, u32& r3, u32 addr) {
    asm volatile("ldmatrix.sync.aligned.m8n8.x4.trans.shared.b16 {%0,%1,%2,%3},[%4];"
                 : "=r"(r0), "=r"(r1), "=r"(r2), "=r"(r3) : "r"(addr));
}
__device__ __forceinline__ void mma_bf16(float* c, const u32* a, u32 b0, u32 b1) {
    asm volatile("mma.sync.aligned.m16n8k16.row.col.f32.bf16.bf16.f32 "
                 "{%0,%1,%2,%3},{%4,%5,%6,%7},{%8,%9},{%0,%1,%2,%3};"
                 : "+f"(c[0]), "+f"(c[1]), "+f"(c[2]), "+f"(c[3])
                 : "r"(a[0]), "r"(a[1]), "r"(a[2]), "r"(a[3]), "r"(b0), "r"(b1));
}
// FFMA-only exp (no MUFU).
__device__ __forceinline__ float fexp(float x) {
    x = fmaxf(x, -80.0f);
    float y = x * 1.4426950408889634f;
    float k = rintf(y);
    float t = (y - k) * 0.6931471805599453f;
    float p = fmaf(t, fmaf(t, fmaf(t, fmaf(t, fmaf(t, 8.3333333e-3f, 4.1666667e-2f),
                 0.16666667f), 0.5f), 1.0f), 1.0f);
    int ki = (int)k;
    return __int_as_float(__float_as_int(p) + (ki << 23));
}

// ---------------- weight conversion ----------------
__global__ void cvt_qkv_kernel(const float* __restrict__ qw, const float* __restrict__ kw,
                               const float* __restrict__ vw, const float* __restrict__ qb,
                               const float* __restrict__ kb, const float* __restrict__ vb)
{
    int gtid = blockIdx.x * blockDim.x + threadIdx.x;
    int stride = gridDim.x * blockDim.x;
    for (int i = gtid; i < C_*C_/4; i += stride) {
        int c = i / (C_/4), j = (i % (C_/4)) * 4;
        float4 q4 = *(const float4*)(qw + (size_t)c*C_ + j);
        float4 k4 = *(const float4*)(kw + (size_t)c*C_ + j);
        float4 v4 = *(const float4*)(vw + (size_t)c*C_ + j);
        *(uint2*)(g_wqkv + (size_t)c*C3 + j)        = make_uint2(pack_bf16(q4.x,q4.y), pack_bf16(q4.z,q4.w));
        *(uint2*)(g_wqkv + (size_t)c*C3 + C_ + j)   = make_uint2(pack_bf16(k4.x,k4.y), pack_bf16(k4.z,k4.w));
        *(uint2*)(g_wqkv + (size_t)c*C3 + 2*C_ + j) = make_uint2(pack_bf16(v4.x,v4.y), pack_bf16(v4.z,v4.w));
    }
    if (gtid < C_) {
        g_bqkv[gtid]        = qb[gtid];
        g_bqkv[C_ + gtid]   = kb[gtid];
        g_bqkv[2*C_ + gtid] = vb[gtid];
    }
}
__global__ void cvt_kernel(const float* __restrict__ src, __nv_bfloat16* __restrict__ dst, int n4)
{
    int gtid = blockIdx.x * blockDim.x + threadIdx.x;
    int stride = gridDim.x * blockDim.x;
    for (int i = gtid; i < n4; i += stride) {
        float4 s = *(const float4*)(src + (size_t)i*4);
        *(uint2*)(dst + (size_t)i*4) = make_uint2(pack_bf16(s.x,s.y), pack_bf16(s.z,s.w));
    }
}

// ---------------- LayerNorm: fp32 in -> bf16 out ----------------
__global__ void __launch_bounds__(256) ln_kernel(const float* __restrict__ x,
                                                 const float* __restrict__ w,
                                                 const float* __restrict__ b,
                                                 __nv_bfloat16* __restrict__ y)
{
    __shared__ float red[8];
    int row = blockIdx.x, tid = threadIdx.x;
    const float* xr = x + (size_t)row * C_;
    float4 v = *(const float4*)(xr + 4*tid);

    float s = v.x + v.y + v.z + v.w;
#pragma unroll
    for (int o = 16; o > 0; o >>= 1) s += __shfl_xor_sync(~0u, s, o);
    if ((tid & 31) == 0) red[tid >> 5] = s;
    __syncthreads();
    if (tid < 32) {
        float t = (tid < 8) ? red[tid] : 0.f;
#pragma unroll
        for (int o = 4; o > 0; o >>= 1) t += __shfl_xor_sync(~0u, t, o);
        if (tid == 0) red[0] = t;
    }
    __syncthreads();
    float mu = red[0] * (1.0f / C_);
    __syncthreads();

    float dx = v.x-mu, dy = v.y-mu, dz = v.z-mu, dw = v.w-mu;
    float sq = dx*dx + dy*dy + dz*dz + dw*dw;
#pragma unroll
    for (int o = 16; o > 0; o >>= 1) sq += __shfl_xor_sync(~0u, sq, o);
    if ((tid & 31) == 0) red[tid >> 5] = sq;
    __syncthreads();
    if (tid < 32) {
        float t = (tid < 8) ? red[tid] : 0.f;
#pragma unroll
        for (int o = 4; o > 0; o >>= 1) t += __shfl_xor_sync(~0u, t, o);
        if (tid == 0) red[0] = t;
    }
    __syncthreads();
    float rs = rsqrtf(red[0] * (1.0f / C_) + 1e-5f);
    float4 w4 = *(const float4*)(w + 4*tid);
    float4 b4 = *(const float4*)(b + 4*tid);
    float o0 = dx*rs*w4.x + b4.x, o1 = dy*rs*w4.y + b4.y;
    float o2 = dz*rs*w4.z + b4.z, o3 = dw*rs*w4.w + b4.w;
    *(uint2*)(y + (size_t)row*C_ + 4*tid) = make_uint2(pack_bf16(o0,o1), pack_bf16(o2,o3));
}

// ---------------- GEMM 128x128x32, 4 warps, warp tile 64x64, 4-stage ----------------
// MODE 0: out = acc + bias               (OBF: bf16 out)
// MODE 1: out = resid + gamma*(acc+bias) (fp32 out)
// MODE 2: out = gelu(acc + bias)         (bf16 out)
#define GA_ROWB   80
#define GB_ROWB   272
#define GA_BYTES  (128*GA_ROWB)         // 10240
#define GB_BYTES  (32*GB_ROWB)          // 8704
#define STAGE_B   (GA_BYTES + GB_BYTES) // 18944
#define NSTAGE    4
#define GEMM_SMEM (NSTAGE*STAGE_B)      // 75776

template<int MODE, int OBF>
__global__ void __launch_bounds__(128) bgemm_kernel(
    const __nv_bfloat16* __restrict__ A, const __nv_bfloat16* __restrict__ Bw,
    const float* __restrict__ bias,
    const float* __restrict__ resid, const float* __restrict__ gamma,
    void* __restrict__ CoutV, int M, int N, int K)
{
    extern __shared__ char gsm[];
    const u32 smb = (u32)__cvta_generic_to_shared(gsm);

    const int tid  = threadIdx.x;
    const int lane = tid & 31, warp = tid >> 5;
    const int warp_m = warp >> 1, warp_n = warp & 1;   // 2 x 2 warp grid, 64x64 tiles
    const int m_blk = blockIdx.y << 7, n_blk = blockIdx.x << 7;

    // cp.async assignments (128 threads, 8 x 16B per thread per stage)
    const int ar = tid >> 2, ac = tid & 3;       // A: rows 0..31 (x4 passes), 4x16B cols
    const int br = tid >> 4, bc = tid & 15;      // B: rows 0..7 (x4 passes), 16x16B cols
    const __nv_bfloat16* Ag = A  + (size_t)(m_blk + ar) * K + ac*8;
    const __nv_bfloat16* Bg = Bw + (size_t)br * N + n_blk + bc*8;
    const u32 dA0 = smb + ar*GA_ROWB + ac*16;
    const u32 dB0 = smb + GA_BYTES + br*GB_ROWB + bc*16;

    // ldmatrix base addressing
    const int g  = lane >> 3;
    const int r8 = lane & 7;
    const u32 aAddr0 = smb + (u32)(warp_m*64 + r8 + (g&1)*8) * GA_ROWB + (u32)((g>>1)*16);
    const u32 bAddr0 = smb + GA_BYTES + (u32)(r8 + (g&1)*8) * GB_ROWB
                           + (u32)(warp_n*64 + (g>>1)*8) * 2;

    float acc[4][8][4];
#pragma unroll
    for (int mt = 0; mt < 4; mt++)
#pragma unroll
        for (int nt = 0; nt < 8; nt++)
#pragma unroll
            for (int i = 0; i < 4; i++) acc[mt][nt][i] = 0.f;

    const int nk = K >> 5;

    auto issue = [&](int kt) {
        const u32 sb = (kt & (NSTAGE-1)) * STAGE_B;
        const __nv_bfloat16* Ak = Ag + (kt << 5);
        const __nv_bfloat16* Bk = Bg + (size_t)(kt << 5) * N;
#pragma unroll
        for (int p = 0; p < 4; p++)
            cp16(dA0 + sb + p*32*GA_ROWB, Ak + (size_t)(p*32)*K);
#pragma unroll
        for (int p = 0; p < 4; p++)
            cp16(dB0 + sb + p*8*GB_ROWB,  Bk + (size_t)(p*8)*N);
        cp_commit();
    };

    issue(0);
    if (nk > 1) issue(1);
    if (nk > 2) issue(2);

    for (int kt = 0; kt < nk; kt++) {
        if      (kt + 2 < nk) asm volatile("cp.async.wait_group 2;");
        else if (kt + 1 < nk) asm volatile("cp.async.wait_group 1;");
        else                  asm volatile("cp.async.wait_group 0;");
        __syncthreads();   // stage (kt+3)%4 was consumed in iter kt-1

        if (kt + 3 < nk) issue(kt + 3);

        const u32 sb = (kt & (NSTAGE-1)) * STAGE_B;
        const u32 aB = aAddr0 + sb;
        const u32 bB = bAddr0 + sb;
#pragma unroll
        for (int ks = 0; ks < 2; ks++) {
            u32 af[4][4];
#pragma unroll
            for (int mt = 0; mt < 4; mt++)
                ldsm_x4(af[mt][0], af[mt][1], af[mt][2], af[mt][3],
                        aB + (u32)(mt*16) * GA_ROWB + (u32)(ks*32));
#pragma unroll
            for (int np = 0; np < 4; np++) {
                u32 b0, b1, b2, b3;
                ldsm_x4_t(b0, b1, b2, b3,
                          bB + (u32)(ks*16) * GB_ROWB + (u32)(np*32));
#pragma unroll
                for (int mt = 0; mt < 4; mt++) {
                    mma_bf16(acc[mt][2*np],   af[mt], b0, b1);
                    mma_bf16(acc[mt][2*np+1], af[mt], b2, b3);
                }
            }
        }
    }

    // ---- epilogue ----
    const int rr = lane >> 2, cc = (lane & 3) << 1;
    const int row0 = m_blk + warp_m * 64;
    const int col0 = n_blk + warp_n * 64;
#pragma unroll
    for (int mt = 0; mt < 4; mt++) {
#pragma unroll
        for (int nt = 0; nt < 8; nt++) {
            const int col = col0 + nt * 8 + cc;
            float2 b2 = *(const float2*)(bias + col);
            float2 g2 = make_float2(0.f, 0.f);
            if (MODE == 1) g2 = *(const float2*)(gamma + col);
#pragma unroll
            for (int half = 0; half < 2; half++) {
                const int row = row0 + mt * 16 + rr + half * 8;
                const size_t off = (size_t)row * N + col;
                float v0 = acc[mt][nt][half*2 + 0] + b2.x;
                float v1 = acc[mt][nt][half*2 + 1] + b2.y;
                if (MODE == 1) {
                    float2 rv = *(const float2*)(resid + off);
                    v0 = rv.x + g2.x * v0;
                    v1 = rv.y + g2.y * v1;
                } else if (MODE == 2) {
                    v0 = 0.5f * v0 * (1.0f + erff(v0 * 0.70710678118654752f));
                    v1 = 0.5f * v1 * (1.0f + erff(v1 * 0.70710678118654752f));
                }
                if (OBF) *(u32*)((__nv_bfloat16*)CoutV + off) = pack_bf16(v0, v1);
                else     *(float2*)((float*)CoutV + off) = make_float2(v0, v1);
            }
        }
    }
}

// ---------------- Flash attention: bf16 MMA, fp32 softmax ----------------
#define KV_ROWB  144
#define TILE_B   (64*KV_ROWB)
#define SQ_OFF   0
#define SK_OFF   (TILE_B)
#define SV_OFF   (3*TILE_B)
#define SMSK_OFF (5*TILE_B)
#define ATTN_SMEM (5*TILE_B + 2*64*4)

__device__ __forceinline__ void attn_issue_kv(const __nv_bfloat16* __restrict__ qkv,
                                              u32 smb, int buf, int kt, int b, int h, int tid)
{
    const __nv_bfloat16* gK = qkv + ((size_t)(b*T_) + kt*64) * C3 + C_ + h*D_;
    const __nv_bfloat16* gV = gK + C_;
    u32 dK = smb + SK_OFF + buf*TILE_B;
    u32 dV = smb + SV_OFF + buf*TILE_B;
#pragma unroll
    for (int k = 0; k < 4; k++) {
        int c = tid + k*128;
        int row = c >> 3, col16 = c & 7;
        cp16(dK + row*KV_ROWB + col16*16, gK + (size_t)row*C3 + col16*8);
        cp16(dV + row*KV_ROWB + col16*16, gV + (size_t)row*C3 + col16*8);
    }
}

__global__ void __launch_bounds__(128) attn_kernel(
    const __nv_bfloat16* __restrict__ qkv, const int* __restrict__ mask,
    __nv_bfloat16* __restrict__ Out)
{
    extern __shared__ char attn_sm[];
    u32 smb = (u32)__cvta_generic_to_shared(attn_sm);
    float* sMask = (float*)(attn_sm + SMSK_OFF);

    const int tid = threadIdx.x;
    const int lane = tid & 31, warp = tid >> 5;
    const int b = blockIdx.z, h = blockIdx.y;
    const int q0 = blockIdx.x << 6;
    const int g = lane >> 3, r8 = lane & 7;
    const int qd = lane >> 2, qi = lane & 3;

    {
        const __nv_bfloat16* gQ = qkv + ((size_t)(b*T_ + q0)) * C3 + h*D_;
#pragma unroll
        for (int k = 0; k < 4; k++) {
            int c = tid + k*128;
            int row = c >> 3, col16 = c & 7;
            cp16(smb + SQ_OFF + row*KV_ROWB + col16*16, gQ + (size_t)row*C3 + col16*8);
        }
        attn_issue_kv(qkv, smb, 0, 0, b, h, tid);
        if (tid < 64) sMask[tid] = mask[b*T_ + tid] ? 0.f : -1e30f;
        cp_commit();
    }

    float ofrag[8][4];
#pragma unroll
    for (int nt = 0; nt < 8; nt++)
#pragma unroll
        for (int i = 0; i < 4; i++) ofrag[nt][i] = 0.f;
    float mrow0 = -1e30f, mrow1 = -1e30f, lrow0 = 0.f, lrow1 = 0.f;
    u32 qf[4][4];

    const int NKT = T_ / 64;
    for (int kt = 0; kt < NKT; kt++) {
        const int cur = kt & 1;
        if (kt + 1 < NKT) {
            attn_issue_kv(qkv, smb, cur ^ 1, kt + 1, b, h, tid);
            if (tid < 64) sMask[(cur^1)*64 + tid] = mask[b*T_ + (kt+1)*64 + tid] ? 0.f : -1e30f;
            cp_commit();
            asm volatile("cp.async.wait_group 1;");
        } else {
            asm volatile("cp.async.wait_group 0;");
        }
        __syncthreads();

        if (kt == 0) {
#pragma unroll
            for (int ks = 0; ks < 4; ks++) {
                u32 addr = smb + SQ_OFF
                         + (u32)(warp*16 + r8 + (g&1)*8) * KV_ROWB
                         + (u32)(ks*16 + (g>>1)*8) * 2;
                ldsm_x4(qf[ks][0], qf[ks][1], qf[ks][2], qf[ks][3], addr);
            }
        }

        float sfrag[8][4];
#pragma unroll
        for (int nt = 0; nt < 8; nt++)
#pragma unroll
            for (int i = 0; i < 4; i++) sfrag[nt][i] = 0.f;
        const u32 kBase = smb + SK_OFF + cur*TILE_B;
#pragma unroll
        for (int ks = 0; ks < 4; ks++) {
#pragma unroll
            for (int np = 0; np < 4; np++) {
                u32 k0, k1, k2, k3;
                u32 addr = kBase + (u32)(np*16 + (g>>1)*8 + r8) * KV_ROWB
                                 + (u32)(ks*16 + (g&1)*8) * 2;
                ldsm_x4(k0, k1, k2, k3, addr);
                mma_bf16(sfrag[2*np],   qf[ks], k0, k1);
                mma_bf16(sfrag[2*np+1], qf[ks], k2, k3);
            }
        }

        const float* msk = sMask + cur*64;
        float mx0 = -1e30f, mx1 = -1e30f;
#pragma unroll
        for (int nt = 0; nt < 8; nt++) {
            float2 am = *(const float2*)(msk + nt*8 + 2*qi);
            sfrag[nt][0] = fmaf(sfrag[nt][0], 0.125f, am.x);
            sfrag[nt][1] = fmaf(sfrag[nt][1], 0.125f, am.y);
            sfrag[nt][2] = fmaf(sfrag[nt][2], 0.125f, am.x);
            sfrag[nt][3] = fmaf(sfrag[nt][3], 0.125f, am.y);
            mx0 = fmaxf(mx0, fmaxf(sfrag[nt][0], sfrag[nt][1]));
            mx1 = fmaxf(mx1, fmaxf(sfrag[nt][2], sfrag[nt][3]));
        }
        mx0 = fmaxf(mx0, __shfl_xor_sync(~0u, mx0, 1));
        mx0 = fmaxf(mx0, __shfl_xor_sync(~0u, mx0, 2));
        mx1 = fmaxf(mx1, __shfl_xor_sync(~0u, mx1, 1));
        mx1 = fmaxf(mx1, __shfl_xor_sync(~0u, mx1, 2));
        float mnew0 = fmaxf(mrow0, mx0), mnew1 = fmaxf(mrow1, mx1);
        float cor0 = fexp(mrow0 - mnew0), cor1 = fexp(mrow1 - mnew1);
        mrow0 = mnew0; mrow1 = mnew1;
        float ps0 = 0.f, ps1 = 0.f;
#pragma unroll
        for (int nt = 0; nt < 8; nt++) {
            sfrag[nt][0] = fexp(sfrag[nt][0] - mnew0);
            sfrag[nt][1] = fexp(sfrag[nt][1] - mnew0);
            sfrag[nt][2] = fexp(sfrag[nt][2] - mnew1);
            sfrag[nt][3] = fexp(sfrag[nt][3] - mnew1);
            ps0 += sfrag[nt][0] + sfrag[nt][1];
            ps1 += sfrag[nt][2] + sfrag[nt][3];
        }
        ps0 += __shfl_xor_sync(~0u, ps0, 1);
        ps0 += __shfl_xor_sync(~0u, ps0, 2);
        ps1 += __shfl_xor_sync(~0u, ps1, 1);
        ps1 += __shfl_xor_sync(~0u, ps1, 2);
        lrow0 = lrow0 * cor0 + ps0;
        lrow1 = lrow1 * cor1 + ps1;
#pragma unroll
        for (int nt = 0; nt < 8; nt++) {
            ofrag[nt][0] *= cor0; ofrag[nt][1] *= cor0;
            ofrag[nt][2] *= cor1; ofrag[nt][3] *= cor1;
        }

        const u32 vBase = smb + SV_OFF + cur*TILE_B;
#pragma unroll
        for (int kk = 0; kk < 4; kk++) {
            u32 a[4];
            a[0] = pack_bf16(sfrag[2*kk][0],   sfrag[2*kk][1]);
            a[1] = pack_bf16(sfrag[2*kk][2],   sfrag[2*kk][3]);
            a[2] = pack_bf16(sfrag[2*kk+1][0], sfrag[2*kk+1][1]);
            a[3] = pack_bf16(sfrag[2*kk+1][2], sfrag[2*kk+1][3]);
#pragma unroll
            for (int dp = 0; dp < 4; dp++) {
                u32 v0, v1, v2, v3;
                u32 addr = vBase + (u32)(kk*16 + r8 + (g&1)*8) * KV_ROWB
                                 + (u32)(dp*16 + (g>>1)*8) * 2;
                ldsm_x4_t(v0, v1, v2, v3, addr);
                mma_bf16(ofrag[2*dp],   a, v0, v1);
                mma_bf16(ofrag[2*dp+1], a, v2, v3);
            }
        }
        __syncthreads();
    }

    const float inv0 = 1.0f / lrow0, inv1 = 1.0f / lrow1;
    const int r0 = q0 + warp*16 + qd;
    const int r1 = r0 + 8;
    __nv_bfloat16* o0 = Out + (size_t)(b*T_ + r0) * C_ + h*D_ + 2*qi;
    __nv_bfloat16* o1 = Out + (size_t)(b*T_ + r1) * C_ + h*D_ + 2*qi;
#pragma unroll
    for (int nt = 0; nt < 8; nt++) {
        *(u32*)(o0 + nt*8) = pack_bf16(ofrag[nt][0]*inv0, ofrag[nt][1]*inv0);
        *(u32*)(o1 + nt*8) = pack_bf16(ofrag[nt][2]*inv1, ofrag[nt][3]*inv1);
    }
}

// ---------------- host launcher ----------------
extern "C" void kernel_launch(void* const* d_in, const int* in_sizes, int n_in,
                              void* d_out, int out_size)
{
    const float* x    = (const float*)d_in[0];
    const int*   mask = (const int*)  d_in[1];
    const float* ln1w = (const float*)d_in[2];
    const float* ln1b = (const float*)d_in[3];
    const float* ln2w = (const float*)d_in[4];
    const float* ln2b = (const float*)d_in[5];
    const float* qw   = (const float*)d_in[6];
    const float* qb   = (const float*)d_in[7];
    const float* kw   = (const float*)d_in[8];
    const float* kb   = (const float*)d_in[9];
    const float* vw   = (const float*)d_in[10];
    const float* vb   = (const float*)d_in[11];
    const float* ow   = (const float*)d_in[12];
    const float* ob   = (const float*)d_in[13];
    const float* f1w  = (const float*)d_in[14];
    const float* f1b  = (const float*)d_in[15];
    const float* f2w  = (const float*)d_in[16];
    const float* f2b  = (const float*)d_in[17];
    const float* gm1  = (const float*)d_in[18];
    const float* gm2  = (const float*)d_in[19];
    float* out = (float*)d_out;

    __nv_bfloat16 *b_h, *b_h2, *b_qkv, *b_att, *b_f1, *b_wqkv, *b_wo, *b_wf1, *b_wf2;
    float *b_x1, *b_bqkv;
    cudaGetSymbolAddress((void**)&b_h,    g_hb);
    cudaGetSymbolAddress((void**)&b_h2,   g_h2b);
    cudaGetSymbolAddress((void**)&b_qkv,  g_qkv);
    cudaGetSymbolAddress((void**)&b_att,  g_attb);
    cudaGetSymbolAddress((void**)&b_f1,   g_f1b);
    cudaGetSymbolAddress((void**)&b_x1,   g_x1);
    cudaGetSymbolAddress((void**)&b_wqkv, g_wqkv);
    cudaGetSymbolAddress((void**)&b_wo,   g_wo);
    cudaGetSymbolAddress((void**)&b_wf1,  g_wf1);
    cudaGetSymbolAddress((void**)&b_wf2,  g_wf2);
    cudaGetSymbolAddress((void**)&b_bqkv, g_bqkv);

    cudaFuncSetAttribute(attn_kernel,
                         cudaFuncAttributeMaxDynamicSharedMemorySize, ATTN_SMEM);
    cudaFuncSetAttribute(bgemm_kernel<0,1>,
                         cudaFuncAttributeMaxDynamicSharedMemorySize, GEMM_SMEM);
    cudaFuncSetAttribute(bgemm_kernel<1,0>,
                         cudaFuncAttributeMaxDynamicSharedMemorySize, GEMM_SMEM);
    cudaFuncSetAttribute(bgemm_kernel<2,1>,
                         cudaFuncAttributeMaxDynamicSharedMemorySize, GEMM_SMEM);

    cvt_qkv_kernel<<<1024, 256>>>(qw, kw, vw, qb, kb, vb);
    cvt_kernel<<<1024, 256>>>(ow,  b_wo,  C_*C_/4);
    cvt_kernel<<<2048, 256>>>(f1w, b_wf1, C_*DFF/4);
    cvt_kernel<<<2048, 256>>>(f2w, b_wf2, DFF*C_/4);

    dim3 gridQKV(C3 / 128, NTOK / 128);
    dim3 gridC  (C_ / 128, NTOK / 128);
    dim3 gridF  (DFF / 128, NTOK / 128);

    ln_kernel<<<NTOK, 256>>>(x, ln1w, ln1b, b_h);
    bgemm_kernel<0,1><<<gridQKV, 128, GEMM_SMEM>>>(b_h, b_wqkv, b_bqkv, nullptr, nullptr, b_qkv, NTOK, C3, C_);
    attn_kernel<<<dim3(T_/64, H_, B_), 128, ATTN_SMEM>>>(b_qkv, mask, b_att);
    bgemm_kernel<1,0><<<gridC, 128, GEMM_SMEM>>>(b_att, b_wo, ob, x, gm1, b_x1, NTOK, C_, C_);
    ln_kernel<<<NTOK, 256>>>(b_x1, ln2w, ln2b, b_h2);
    bgemm_kernel<2,1><<<gridF, 128, GEMM_SMEM>>>(b_h2, b_wf1, f1b, nullptr, nullptr, b_f1, NTOK, DFF, C_);
    bgemm_kernel<1,0><<<gridC, 128, GEMM_SMEM>>>(b_f1, b_wf2, f2b, b_x1, gm2, out, NTOK, C_, DFF);
}

// round 9
// speedup vs baseline: 1.1655x; 1.0077x over previous
#include <cuda_runtime.h>
#include <cuda_bf16.h>
#include <cstdint>
#include <math.h>

typedef unsigned int u32;

#define B_   2
#define T_   2048
#define C_   1024
#define H_   16
#define D_   64
#define NTOK (B_*T_)
#define DFF  4096
#define C3   (3*C_)

// ---------------- scratch (no allocation allowed) ----------------
__device__ __nv_bfloat16 g_hb  [NTOK*C_];
__device__ __nv_bfloat16 g_h2b [NTOK*C_];
__device__ __nv_bfloat16 g_qkv [NTOK*C3];
__device__ __nv_bfloat16 g_attb[NTOK*C_];
__device__ __nv_bfloat16 g_f1b [(size_t)NTOK*DFF];
__device__ float         g_x1  [NTOK*C_];
__device__ __nv_bfloat16 g_wqkv[C_*C3];
__device__ __nv_bfloat16 g_wo  [C_*C_];
__device__ __nv_bfloat16 g_wf1 [C_*DFF];
__device__ __nv_bfloat16 g_wf2 [DFF*C_];
__device__ float         g_bqkv[C3];

// ---------------- small helpers ----------------
__device__ __forceinline__ u32 pack_bf16(float x, float y) {
    __nv_bfloat162 t = __floats2bfloat162_rn(x, y);
    u32 r; memcpy(&r, &t, 4); return r;
}
__device__ __forceinline__ void cp16(u32 sdst, const void* gsrc) {
    asm volatile("cp.async.cg.shared.global [%0], [%1], 16;" :: "r"(sdst), "l"(gsrc));
}
__device__ __forceinline__ void cp_commit() { asm volatile("cp.async.commit_group;"); }
__device__ __forceinline__ void ldsm_x4(u32& r0, u32& r1, u32& r2, u32& r3, u32 addr) {
    asm volatile("ldmatrix.sync.aligned.m8n8.x4.shared.b16 {%0,%1,%2,%3},[%4];"
                 : "=r"(r0), "=r"(r1), "=r"(r2), "=r"(r3) : "r"(addr));
}
__device__ __forceinline__ void ldsm_x4_t(u32& r0, u32& r1, u32& r2, u32& r3, u32 addr) {
    asm volatile("ldmatrix.sync.aligned.m8n8.x4.trans.shared.b16 {%0,%1,%2,%3},[%4];"
                 : "=r"(r0), "=r"(r1), "=r"(r2), "=r"(r3) : "r"(addr));
}
__device__ __forceinline__ void mma_bf16(float* c, const u32* a, u32 b0, u32 b1) {
    asm volatile("mma.sync.aligned.m16n8k16.row.col.f32.bf16.bf16.f32 "
                 "{%0,%1,%2,%3},{%4,%5,%6,%7},{%8,%9},{%0,%1,%2,%3};"
                 : "+f"(c[0]), "+f"(c[1]), "+f"(c[2]), "+f"(c[3])
                 : "r"(a[0]), "r"(a[1]), "r"(a[2]), "r"(a[3]), "r"(b0), "r"(b1));
}
// FFMA-only exp (no MUFU).
__device__ __forceinline__ float fexp(float x) {
    x = fmaxf(x, -80.0f);
    float y = x * 1.4426950408889634f;
    float k = rintf(y);
    float t = (y - k) * 0.6931471805599453f;
    float p = fmaf(t, fmaf(t, fmaf(t, fmaf(t, fmaf(t, 8.3333333e-3f, 4.1666667e-2f),
                 0.16666667f), 0.5f), 1.0f), 1.0f);
    int ki = (int)k;
    return __int_as_float(__float_as_int(p) + (ki << 23));
}

// ---------------- weight conversion ----------------
__global__ void cvt_qkv_kernel(const float* __restrict__ qw, const float* __restrict__ kw,
                               const float* __restrict__ vw, const float* __restrict__ qb,
                               const float* __restrict__ kb, const float* __restrict__ vb)
{
    int gtid = blockIdx.x * blockDim.x + threadIdx.x;
    int stride = gridDim.x * blockDim.x;
    for (int i = gtid; i < C_*C_/4; i += stride) {
        int c = i / (C_/4), j = (i % (C_/4)) * 4;
        float4 q4 = *(const float4*)(qw + (size_t)c*C_ + j);
        float4 k4 = *(const float4*)(kw + (size_t)c*C_ + j);
        float4 v4 = *(const float4*)(vw + (size_t)c*C_ + j);
        *(uint2*)(g_wqkv + (size_t)c*C3 + j)        = make_uint2(pack_bf16(q4.x,q4.y), pack_bf16(q4.z,q4.w));
        *(uint2*)(g_wqkv + (size_t)c*C3 + C_ + j)   = make_uint2(pack_bf16(k4.x,k4.y), pack_bf16(k4.z,k4.w));
        *(uint2*)(g_wqkv + (size_t)c*C3 + 2*C_ + j) = make_uint2(pack_bf16(v4.x,v4.y), pack_bf16(v4.z,v4.w));
    }
    if (gtid < C_) {
        g_bqkv[gtid]        = qb[gtid];
        g_bqkv[C_ + gtid]   = kb[gtid];
        g_bqkv[2*C_ + gtid] = vb[gtid];
    }
}
// fused convert of O/FF1/FF2 weights (one launch)
__global__ void cvt3_kernel(const float* __restrict__ ow, const float* __restrict__ f1w,
                            const float* __restrict__ f2w)
{
    int gtid = blockIdx.x * blockDim.x + threadIdx.x;
    int stride = gridDim.x * blockDim.x;
    const int n_o  = C_*C_/4;
    const int n_f  = C_*DFF/4;
    for (int i = gtid; i < n_o; i += stride) {
        float4 s = *(const float4*)(ow + (size_t)i*4);
        *(uint2*)(g_wo + (size_t)i*4) = make_uint2(pack_bf16(s.x,s.y), pack_bf16(s.z,s.w));
    }
    for (int i = gtid; i < n_f; i += stride) {
        float4 s = *(const float4*)(f1w + (size_t)i*4);
        *(uint2*)(g_wf1 + (size_t)i*4) = make_uint2(pack_bf16(s.x,s.y), pack_bf16(s.z,s.w));
    }
    for (int i = gtid; i < n_f; i += stride) {
        float4 s = *(const float4*)(f2w + (size_t)i*4);
        *(uint2*)(g_wf2 + (size_t)i*4) = make_uint2(pack_bf16(s.x,s.y), pack_bf16(s.z,s.w));
    }
}

// ---------------- LayerNorm: fp32 in -> bf16 out ----------------
__global__ void __launch_bounds__(256) ln_kernel(const float* __restrict__ x,
                                                 const float* __restrict__ w,
                                                 const float* __restrict__ b,
                                                 __nv_bfloat16* __restrict__ y)
{
    __shared__ float red[8];
    int row = blockIdx.x, tid = threadIdx.x;
    const float* xr = x + (size_t)row * C_;
    float4 v = *(const float4*)(xr + 4*tid);

    float s = v.x + v.y + v.z + v.w;
#pragma unroll
    for (int o = 16; o > 0; o >>= 1) s += __shfl_xor_sync(~0u, s, o);
    if ((tid & 31) == 0) red[tid >> 5] = s;
    __syncthreads();
    if (tid < 32) {
        float t = (tid < 8) ? red[tid] : 0.f;
#pragma unroll
        for (int o = 4; o > 0; o >>= 1) t += __shfl_xor_sync(~0u, t, o);
        if (tid == 0) red[0] = t;
    }
    __syncthreads();
    float mu = red[0] * (1.0f / C_);
    __syncthreads();

    float dx = v.x-mu, dy = v.y-mu, dz = v.z-mu, dw = v.w-mu;
    float sq = dx*dx + dy*dy + dz*dz + dw*dw;
#pragma unroll
    for (int o = 16; o > 0; o >>= 1) sq += __shfl_xor_sync(~0u, sq, o);
    if ((tid & 31) == 0) red[tid >> 5] = sq;
    __syncthreads();
    if (tid < 32) {
        float t = (tid < 8) ? red[tid] : 0.f;
#pragma unroll
        for (int o = 4; o > 0; o >>= 1) t += __shfl_xor_sync(~0u, t, o);
        if (tid == 0) red[0] = t;
    }
    __syncthreads();
    float rs = rsqrtf(red[0] * (1.0f / C_) + 1e-5f);
    float4 w4 = *(const float4*)(w + 4*tid);
    float4 b4 = *(const float4*)(b + 4*tid);
    float o0 = dx*rs*w4.x + b4.x, o1 = dy*rs*w4.y + b4.y;
    float o2 = dz*rs*w4.z + b4.z, o3 = dw*rs*w4.w + b4.w;
    *(uint2*)(y + (size_t)row*C_ + 4*tid) = make_uint2(pack_bf16(o0,o1), pack_bf16(o2,o3));
}

// ---------------- GEMM 128x128x32, 4 warps, warp tile 64x64, 4-stage ----------------
#define GA_ROWB   80
#define GB_ROWB   272
#define GA_BYTES  (128*GA_ROWB)
#define GB_BYTES  (32*GB_ROWB)
#define STAGE_B   (GA_BYTES + GB_BYTES)
#define NSTAGE    4
#define GEMM_SMEM (NSTAGE*STAGE_B)

template<int MODE, int OBF>
__global__ void __launch_bounds__(128) bgemm_kernel(
    const __nv_bfloat16* __restrict__ A, const __nv_bfloat16* __restrict__ Bw,
    const float* __restrict__ bias,
    const float* __restrict__ resid, const float* __restrict__ gamma,
    void* __restrict__ CoutV, int M, int N, int K)
{
    extern __shared__ char gsm[];
    const u32 smb = (u32)__cvta_generic_to_shared(gsm);

    const int tid  = threadIdx.x;
    const int lane = tid & 31, warp = tid >> 5;
    const int warp_m = warp >> 1, warp_n = warp & 1;
    const int m_blk = blockIdx.y << 7, n_blk = blockIdx.x << 7;

    const int ar = tid >> 2, ac = tid & 3;
    const int br = tid >> 4, bc = tid & 15;
    const __nv_bfloat16* Ag = A  + (size_t)(m_blk + ar) * K + ac*8;
    const __nv_bfloat16* Bg = Bw + (size_t)br * N + n_blk + bc*8;
    const u32 dA0 = smb + ar*GA_ROWB + ac*16;
    const u32 dB0 = smb + GA_BYTES + br*GB_ROWB + bc*16;

    const int g  = lane >> 3;
    const int r8 = lane & 7;
    const u32 aAddr0 = smb + (u32)(warp_m*64 + r8 + (g&1)*8) * GA_ROWB + (u32)((g>>1)*16);
    const u32 bAddr0 = smb + GA_BYTES + (u32)(r8 + (g&1)*8) * GB_ROWB
                           + (u32)(warp_n*64 + (g>>1)*8) * 2;

    float acc[4][8][4];
#pragma unroll
    for (int mt = 0; mt < 4; mt++)
#pragma unroll
        for (int nt = 0; nt < 8; nt++)
#pragma unroll
            for (int i = 0; i < 4; i++) acc[mt][nt][i] = 0.f;

    const int nk = K >> 5;

    auto issue = [&](int kt) {
        const u32 sb = (kt & (NSTAGE-1)) * STAGE_B;
        const __nv_bfloat16* Ak = Ag + (kt << 5);
        const __nv_bfloat16* Bk = Bg + (size_t)(kt << 5) * N;
#pragma unroll
        for (int p = 0; p < 4; p++)
            cp16(dA0 + sb + p*32*GA_ROWB, Ak + (size_t)(p*32)*K);
#pragma unroll
        for (int p = 0; p < 4; p++)
            cp16(dB0 + sb + p*8*GB_ROWB,  Bk + (size_t)(p*8)*N);
        cp_commit();
    };

    issue(0);
    if (nk > 1) issue(1);
    if (nk > 2) issue(2);

    for (int kt = 0; kt < nk; kt++) {
        if      (kt + 2 < nk) asm volatile("cp.async.wait_group 2;");
        else if (kt + 1 < nk) asm volatile("cp.async.wait_group 1;");
        else                  asm volatile("cp.async.wait_group 0;");
        __syncthreads();

        if (kt + 3 < nk) issue(kt + 3);

        const u32 sb = (kt & (NSTAGE-1)) * STAGE_B;
        const u32 aB = aAddr0 + sb;
        const u32 bB = bAddr0 + sb;
#pragma unroll
        for (int ks = 0; ks < 2; ks++) {
            u32 af[4][4];
#pragma unroll
            for (int mt = 0; mt < 4; mt++)
                ldsm_x4(af[mt][0], af[mt][1], af[mt][2], af[mt][3],
                        aB + (u32)(mt*16) * GA_ROWB + (u32)(ks*32));
#pragma unroll
            for (int np = 0; np < 4; np++) {
                u32 b0, b1, b2, b3;
                ldsm_x4_t(b0, b1, b2, b3,
                          bB + (u32)(ks*16) * GB_ROWB + (u32)(np*32));
#pragma unroll
                for (int mt = 0; mt < 4; mt++) {
                    mma_bf16(acc[mt][2*np],   af[mt], b0, b1);
                    mma_bf16(acc[mt][2*np+1], af[mt], b2, b3);
                }
            }
        }
    }

    const int rr = lane >> 2, cc = (lane & 3) << 1;
    const int row0 = m_blk + warp_m * 64;
    const int col0 = n_blk + warp_n * 64;
#pragma unroll
    for (int mt = 0; mt < 4; mt++) {
#pragma unroll
        for (int nt = 0; nt < 8; nt++) {
            const int col = col0 + nt * 8 + cc;
            float2 b2 = *(const float2*)(bias + col);
            float2 g2 = make_float2(0.f, 0.f);
            if (MODE == 1) g2 = *(const float2*)(gamma + col);
#pragma unroll
            for (int half = 0; half < 2; half++) {
                const int row = row0 + mt * 16 + rr + half * 8;
                const size_t off = (size_t)row * N + col;
                float v0 = acc[mt][nt][half*2 + 0] + b2.x;
                float v1 = acc[mt][nt][half*2 + 1] + b2.y;
                if (MODE == 1) {
                    float2 rv = *(const float2*)(resid + off);
                    v0 = rv.x + g2.x * v0;
                    v1 = rv.y + g2.y * v1;
                } else if (MODE == 2) {
                    v0 = 0.5f * v0 * (1.0f + erff(v0 * 0.70710678118654752f));
                    v1 = 0.5f * v1 * (1.0f + erff(v1 * 0.70710678118654752f));
                }
                if (OBF) *(u32*)((__nv_bfloat16*)CoutV + off) = pack_bf16(v0, v1);
                else     *(float2*)((float*)CoutV + off) = make_float2(v0, v1);
            }
        }
    }
}

// ---------------- Flash attention: 128 queries/CTA, 8 warps ----------------
#define KV_ROWB  144
#define QTILE_B  (128*KV_ROWB)            // 18432
#define KVTILE_B (64*KV_ROWB)             // 9216
#define SQ_OFF   0
#define SK_OFF   (QTILE_B)
#define SV_OFF   (QTILE_B + 2*KVTILE_B)
#define SMSK_OFF (QTILE_B + 4*KVTILE_B)
#define ATTN_SMEM (SMSK_OFF + 2*64*4)

__device__ __forceinline__ void attn_issue_kv(const __nv_bfloat16* __restrict__ qkv,
                                              u32 smb, int buf, int kt, int b, int h, int tid)
{
    const __nv_bfloat16* gK = qkv + ((size_t)(b*T_) + kt*64) * C3 + C_ + h*D_;
    const __nv_bfloat16* gV = gK + C_;
    u32 dK = smb + SK_OFF + buf*KVTILE_B;
    u32 dV = smb + SV_OFF + buf*KVTILE_B;
#pragma unroll
    for (int k = 0; k < 2; k++) {
        int c = tid + k*256;
        int row = c >> 3, col16 = c & 7;
        cp16(dK + row*KV_ROWB + col16*16, gK + (size_t)row*C3 + col16*8);
        cp16(dV + row*KV_ROWB + col16*16, gV + (size_t)row*C3 + col16*8);
    }
}

__global__ void __launch_bounds__(256) attn_kernel(
    const __nv_bfloat16* __restrict__ qkv, const int* __restrict__ mask,
    __nv_bfloat16* __restrict__ Out)
{
    extern __shared__ char attn_sm[];
    u32 smb = (u32)__cvta_generic_to_shared(attn_sm);
    float* sMask = (float*)(attn_sm + SMSK_OFF);

    const int tid = threadIdx.x;
    const int lane = tid & 31, warp = tid >> 5;
    const int b = blockIdx.z, h = blockIdx.y;
    const int q0 = blockIdx.x << 7;      // 128 queries per CTA
    const int g = lane >> 3, r8 = lane & 7;
    const int qd = lane >> 2, qi = lane & 3;

    {
        const __nv_bfloat16* gQ = qkv + ((size_t)(b*T_ + q0)) * C3 + h*D_;
#pragma unroll
        for (int k = 0; k < 4; k++) {
            int c = tid + k*256;
            int row = c >> 3, col16 = c & 7;
            cp16(smb + SQ_OFF + row*KV_ROWB + col16*16, gQ + (size_t)row*C3 + col16*8);
        }
        attn_issue_kv(qkv, smb, 0, 0, b, h, tid);
        if (tid < 64) sMask[tid] = mask[b*T_ + tid] ? 0.f : -1e30f;
        cp_commit();
    }

    float ofrag[8][4];
#pragma unroll
    for (int nt = 0; nt < 8; nt++)
#pragma unroll
        for (int i = 0; i < 4; i++) ofrag[nt][i] = 0.f;
    float mrow0 = -1e30f, mrow1 = -1e30f, lrow0 = 0.f, lrow1 = 0.f;
    u32 qf[4][4];

    const int NKT = T_ / 64;
    for (int kt = 0; kt < NKT; kt++) {
        const int cur = kt & 1;
        if (kt + 1 < NKT) {
            attn_issue_kv(qkv, smb, cur ^ 1, kt + 1, b, h, tid);
            if (tid < 64) sMask[(cur^1)*64 + tid] = mask[b*T_ + (kt+1)*64 + tid] ? 0.f : -1e30f;
            cp_commit();
            asm volatile("cp.async.wait_group 1;");
        } else {
            asm volatile("cp.async.wait_group 0;");
        }
        __syncthreads();

        if (kt == 0) {
#pragma unroll
            for (int ks = 0; ks < 4; ks++) {
                u32 addr = smb + SQ_OFF
                         + (u32)(warp*16 + r8 + (g&1)*8) * KV_ROWB
                         + (u32)(ks*16 + (g>>1)*8) * 2;
                ldsm_x4(qf[ks][0], qf[ks][1], qf[ks][2], qf[ks][3], addr);
            }
        }

        float sfrag[8][4];
#pragma unroll
        for (int nt = 0; nt < 8; nt++)
#pragma unroll
            for (int i = 0; i < 4; i++) sfrag[nt][i] = 0.f;
        const u32 kBase = smb + SK_OFF + cur*KVTILE_B;
#pragma unroll
        for (int ks = 0; ks < 4; ks++) {
#pragma unroll
            for (int np = 0; np < 4; np++) {
                u32 k0, k1, k2, k3;
                u32 addr = kBase + (u32)(np*16 + (g>>1)*8 + r8) * KV_ROWB
                                 + (u32)(ks*16 + (g&1)*8) * 2;
                ldsm_x4(k0, k1, k2, k3, addr);
                mma_bf16(sfrag[2*np],   qf[ks], k0, k1);
                mma_bf16(sfrag[2*np+1], qf[ks], k2, k3);
            }
        }

        const float* msk = sMask + cur*64;
        float mx0 = -1e30f, mx1 = -1e30f;
#pragma unroll
        for (int nt = 0; nt < 8; nt++) {
            float2 am = *(const float2*)(msk + nt*8 + 2*qi);
            sfrag[nt][0] = fmaf(sfrag[nt][0], 0.125f, am.x);
            sfrag[nt][1] = fmaf(sfrag[nt][1], 0.125f, am.y);
            sfrag[nt][2] = fmaf(sfrag[nt][2], 0.125f, am.x);
            sfrag[nt][3] = fmaf(sfrag[nt][3], 0.125f, am.y);
            mx0 = fmaxf(mx0, fmaxf(sfrag[nt][0], sfrag[nt][1]));
            mx1 = fmaxf(mx1, fmaxf(sfrag[nt][2], sfrag[nt][3]));
        }
        mx0 = fmaxf(mx0, __shfl_xor_sync(~0u, mx0, 1));
        mx0 = fmaxf(mx0, __shfl_xor_sync(~0u, mx0, 2));
        mx1 = fmaxf(mx1, __shfl_xor_sync(~0u, mx1, 1));
        mx1 = fmaxf(mx1, __shfl_xor_sync(~0u, mx1, 2));
        float mnew0 = fmaxf(mrow0, mx0), mnew1 = fmaxf(mrow1, mx1);
        float cor0 = fexp(mrow0 - mnew0), cor1 = fexp(mrow1 - mnew1);
        mrow0 = mnew0; mrow1 = mnew1;
        float ps0 = 0.f, ps1 = 0.f;
#pragma unroll
        for (int nt = 0; nt < 8; nt++) {
            sfrag[nt][0] = fexp(sfrag[nt][0] - mnew0);
            sfrag[nt][1] = fexp(sfrag[nt][1] - mnew0);
            sfrag[nt][2] = fexp(sfrag[nt][2] - mnew1);
            sfrag[nt][3] = fexp(sfrag[nt][3] - mnew1);
            ps0 += sfrag[nt][0] + sfrag[nt][1];
            ps1 += sfrag[nt][2] + sfrag[nt][3];
        }
        ps0 += __shfl_xor_sync(~0u, ps0, 1);
        ps0 += __shfl_xor_sync(~0u, ps0, 2);
        ps1 += __shfl_xor_sync(~0u, ps1, 1);
        ps1 += __shfl_xor_sync(~0u, ps1, 2);
        lrow0 = lrow0 * cor0 + ps0;
        lrow1 = lrow1 * cor1 + ps1;
#pragma unroll
        for (int nt = 0; nt < 8; nt++) {
            ofrag[nt][0] *= cor0; ofrag[nt][1] *= cor0;
            ofrag[nt][2] *= cor1; ofrag[nt][3] *= cor1;
        }

        const u32 vBase = smb + SV_OFF + cur*KVTILE_B;
#pragma unroll
        for (int kk = 0; kk < 4; kk++) {
            u32 a[4];
            a[0] = pack_bf16(sfrag[2*kk][0],   sfrag[2*kk][1]);
            a[1] = pack_bf16(sfrag[2*kk][2],   sfrag[2*kk][3]);
            a[2] = pack_bf16(sfrag[2*kk+1][0], sfrag[2*kk+1][1]);
            a[3] = pack_bf16(sfrag[2*kk+1][2], sfrag[2*kk+1][3]);
#pragma unroll
            for (int dp = 0; dp < 4; dp++) {
                u32 v0, v1, v2, v3;
                u32 addr = vBase + (u32)(kk*16 + r8 + (g&1)*8) * KV_ROWB
                                 + (u32)(dp*16 + (g>>1)*8) * 2;
                ldsm_x4_t(v0, v1, v2, v3, addr);
                mma_bf16(ofrag[2*dp],   a, v0, v1);
                mma_bf16(ofrag[2*dp+1], a, v2, v3);
            }
        }
        __syncthreads();
    }

    const float inv0 = 1.0f / lrow0, inv1 = 1.0f / lrow1;
    const int r0 = q0 + warp*16 + qd;
    const int r1 = r0 + 8;
    __nv_bfloat16* o0 = Out + (size_t)(b*T_ + r0) * C_ + h*D_ + 2*qi;
    __nv_bfloat16* o1 = Out + (size_t)(b*T_ + r1) * C_ + h*D_ + 2*qi;
#pragma unroll
    for (int nt = 0; nt < 8; nt++) {
        *(u32*)(o0 + nt*8) = pack_bf16(ofrag[nt][0]*inv0, ofrag[nt][1]*inv0);
        *(u32*)(o1 + nt*8) = pack_bf16(ofrag[nt][2]*inv1, ofrag[nt][3]*inv1);
    }
}

// ---------------- host launcher ----------------
extern "C" void kernel_launch(void* const* d_in, const int* in_sizes, int n_in,
                              void* d_out, int out_size)
{
    const float* x    = (const float*)d_in[0];
    const int*   mask = (const int*)  d_in[1];
    const float* ln1w = (const float*)d_in[2];
    const float* ln1b = (const float*)d_in[3];
    const float* ln2w = (const float*)d_in[4];
    const float* ln2b = (const float*)d_in[5];
    const float* qw   = (const float*)d_in[6];
    const float* qb   = (const float*)d_in[7];
    const float* kw   = (const float*)d_in[8];
    const float* kb   = (const float*)d_in[9];
    const float* vw   = (const float*)d_in[10];
    const float* vb   = (const float*)d_in[11];
    const float* ow   = (const float*)d_in[12];
    const float* ob   = (const float*)d_in[13];
    const float* f1w  = (const float*)d_in[14];
    const float* f1b  = (const float*)d_in[15];
    const float* f2w  = (const float*)d_in[16];
    const float* f2b  = (const float*)d_in[17];
    const float* gm1  = (const float*)d_in[18];
    const float* gm2  = (const float*)d_in[19];
    float* out = (float*)d_out;

    __nv_bfloat16 *b_h, *b_h2, *b_qkv, *b_att, *b_f1, *b_wqkv, *b_wo, *b_wf1, *b_wf2;
    float *b_x1, *b_bqkv;
    cudaGetSymbolAddress((void**)&b_h,    g_hb);
    cudaGetSymbolAddress((void**)&b_h2,   g_h2b);
    cudaGetSymbolAddress((void**)&b_qkv,  g_qkv);
    cudaGetSymbolAddress((void**)&b_att,  g_attb);
    cudaGetSymbolAddress((void**)&b_f1,   g_f1b);
    cudaGetSymbolAddress((void**)&b_x1,   g_x1);
    cudaGetSymbolAddress((void**)&b_wqkv, g_wqkv);
    cudaGetSymbolAddress((void**)&b_wo,   g_wo);
    cudaGetSymbolAddress((void**)&b_wf1,  g_wf1);
    cudaGetSymbolAddress((void**)&b_wf2,  g_wf2);
    cudaGetSymbolAddress((void**)&b_bqkv, g_bqkv);

    cudaFuncSetAttribute(attn_kernel,
                         cudaFuncAttributeMaxDynamicSharedMemorySize, ATTN_SMEM);
    cudaFuncSetAttribute(bgemm_kernel<0,1>,
                         cudaFuncAttributeMaxDynamicSharedMemorySize, GEMM_SMEM);
    cudaFuncSetAttribute(bgemm_kernel<1,0>,
                         cudaFuncAttributeMaxDynamicSharedMemorySize, GEMM_SMEM);
    cudaFuncSetAttribute(bgemm_kernel<2,1>,
                         cudaFuncAttributeMaxDynamicSharedMemorySize, GEMM_SMEM);

    cvt_qkv_kernel<<<1024, 256>>>(qw, kw, vw, qb, kb, vb);
    cvt3_kernel<<<2048, 256>>>(ow, f1w, f2w);

    dim3 gridQKV(C3 / 128, NTOK / 128);
    dim3 gridC  (C_ / 128, NTOK / 128);
    dim3 gridF  (DFF / 128, NTOK / 128);

    ln_kernel<<<NTOK, 256>>>(x, ln1w, ln1b, b_h);
    bgemm_kernel<0,1><<<gridQKV, 128, GEMM_SMEM>>>(b_h, b_wqkv, b_bqkv, nullptr, nullptr, b_qkv, NTOK, C3, C_);
    attn_kernel<<<dim3(T_/128, H_, B_), 256, ATTN_SMEM>>>(b_qkv, mask, b_att);
    bgemm_kernel<1,0><<<gridC, 128, GEMM_SMEM>>>(b_att, b_wo, ob, x, gm1, b_x1, NTOK, C_, C_);
    ln_kernel<<<NTOK, 256>>>(b_x1, ln2w, ln2b, b_h2);
    bgemm_kernel<2,1><<<gridF, 128, GEMM_SMEM>>>(b_h2, b_wf1, f1b, nullptr, nullptr, b_f1, NTOK, DFF, C_);
    bgemm_kernel<1,0><<<gridC, 128, GEMM_SMEM>>>(b_f1, b_wf2, f2b, b_x1, gm2, out, NTOK, C_, DFF);
}